// round 13
// baseline (speedup 1.0000x reference)
#include <cuda_runtime.h>
#include <cuda_bf16.h>
#include <stdint.h>
#include <math.h>

#define BB 32
#define SS 512
#define DD 512
#define HH 8
#define DFF 64
#define SCP 516   // padded score-row stride (words)

// Scratch (allocation-free)
__device__ float g_CT[BB*SS*DD];
__device__ float g_DF[BB*SS*SS];      // exp(sigmoid(qd)) precomputed

// bf16 hi/lo split operand buffers (GEMM inputs)
__device__ __nv_bfloat16 g_Ah[3][BB*SS*DD];
__device__ __nv_bfloat16 g_Al[3][BB*SS*DD];
__device__ __nv_bfloat16 g_Wh[3][DD*DD];
__device__ __nv_bfloat16 g_Wl[3][DD*DD];

// attention operands (written by projection epilogue)
__device__ __nv_bfloat16 g_Qh[BB*HH*SS*DFF];   // [bh][s][df], pre-scaled 1/8
__device__ __nv_bfloat16 g_Ql[BB*HH*SS*DFF];
__device__ __nv_bfloat16 g_Kh[BB*HH*SS*DFF];   // [bh][s][df]
__device__ __nv_bfloat16 g_Kl[BB*HH*SS*DFF];
__device__ __nv_bfloat16 g_Vh[BB*HH*DFF*SS];   // [bh][df][s]  (transposed)
__device__ __nv_bfloat16 g_Vl[BB*HH*DFF*SS];

// ===========================================================================
// PTX helpers (portable sm_80+ subset)
// ===========================================================================
__device__ __forceinline__ unsigned int smem_to_u32(const void* p) {
    unsigned int a;
    asm("{ .reg .u64 t; cvta.to.shared.u64 t, %1; cvt.u32.u64 %0, t; }"
        : "=r"(a) : "l"(p));
    return a;
}

__device__ __forceinline__ void cp_async16(unsigned int dst, const void* src) {
    asm volatile("cp.async.cg.shared.global [%0], [%1], 16;\n"
                 :: "r"(dst), "l"(src));
}
#define CP_COMMIT() asm volatile("cp.async.commit_group;\n" ::: "memory")
#define CP_WAIT1()  asm volatile("cp.async.wait_group 1;\n" ::: "memory")
#define CP_WAIT0()  asm volatile("cp.async.wait_group 0;\n" ::: "memory")

__device__ __forceinline__ void ldmatrix_x4(unsigned int* r, unsigned int addr) {
    asm volatile("ldmatrix.sync.aligned.m8n8.x4.shared.b16 {%0,%1,%2,%3}, [%4];"
                 : "=r"(r[0]), "=r"(r[1]), "=r"(r[2]), "=r"(r[3]) : "r"(addr));
}

__device__ __forceinline__ void mma_bf16(float* c, const unsigned int* a,
                                         unsigned int b0, unsigned int b1) {
    asm volatile(
        "mma.sync.aligned.m16n8k16.row.col.f32.bf16.bf16.f32 "
        "{%0,%1,%2,%3}, {%4,%5,%6,%7}, {%8,%9}, {%0,%1,%2,%3};"
        : "+f"(c[0]), "+f"(c[1]), "+f"(c[2]), "+f"(c[3])
        : "r"(a[0]), "r"(a[1]), "r"(a[2]), "r"(a[3]), "r"(b0), "r"(b1));
}

__device__ __forceinline__ unsigned int bfpack(float x, float y) {
    __nv_bfloat16 h0 = __float2bfloat16(x), h1 = __float2bfloat16(y);
    return (unsigned int)__bfloat16_as_ushort(h0) |
           ((unsigned int)__bfloat16_as_ushort(h1) << 16);
}

// ===========================================================================
// Precompute diff = exp(sigmoid(qd))
// ===========================================================================
__global__ __launch_bounds__(256)
void diff_kernel(const float* __restrict__ qd)
{
    int idx = (blockIdx.x * 256 + threadIdx.x) << 2;
    float4 a = *(const float4*)(qd + idx);
    float4 o;
    o.x = __expf(1.f / (1.f + __expf(-a.x)));
    o.y = __expf(1.f / (1.f + __expf(-a.y)));
    o.z = __expf(1.f / (1.f + __expf(-a.z)));
    o.w = __expf(1.f / (1.f + __expf(-a.w)));
    *(float4*)(g_DF + idx) = o;
}

// ===========================================================================
// Convert fp32 -> bf16 hi/lo split.  which: 0-2 inputs, 3-5 weights, 6: g_CT
// ===========================================================================
__global__ __launch_bounds__(256)
void convert_split(const float* __restrict__ src_in, int which, int n)
{
    const float* src = (which == 6) ? g_CT : src_in;
    __nv_bfloat16 *hi, *lo;
    if (which < 3)      { hi = g_Ah[which];   lo = g_Al[which]; }
    else if (which < 6) { hi = g_Wh[which-3]; lo = g_Wl[which-3]; }
    else                { hi = g_Ah[0];       lo = g_Al[0]; }

    int idx = (blockIdx.x * 256 + threadIdx.x) << 3;
    if (idx >= n) return;
    float4 a = *(const float4*)(src + idx);
    float4 b = *(const float4*)(src + idx + 4);
    float v[8] = {a.x, a.y, a.z, a.w, b.x, b.y, b.z, b.w};
    unsigned int hw[4], lw[4];
    #pragma unroll
    for (int i = 0; i < 4; i++) {
        float x = v[2*i], y = v[2*i+1];
        __nv_bfloat16 h0 = __float2bfloat16(x), h1 = __float2bfloat16(y);
        float r0 = x - __bfloat162float(h0), r1 = y - __bfloat162float(h1);
        hw[i] = (unsigned int)__bfloat16_as_ushort(h0) |
                ((unsigned int)__bfloat16_as_ushort(h1) << 16);
        lw[i] = bfpack(r0, r1);
    }
    *(uint4*)(hi + idx) = make_uint4(hw[0], hw[1], hw[2], hw[3]);
    *(uint4*)(lo + idx) = make_uint4(lw[0], lw[1], lw[2], lw[3]);
}

// ===========================================================================
// mma.sync bf16 3-term split GEMM.  Tile 128x128, BK=32, 3-stage cp.async.
// MODE 0: C -> Cout (fp32 row-major).  MODE 1: z=0/1 -> g_Qh/l,g_Kh/l
// ([bh][s][df], Q scaled 1/8); z=2 -> g_Vh/l transposed [bh][df][s].
// ===========================================================================
#define STG_STRIDE 32768
#define AH_OFF 0
#define AL_OFF 8192
#define BH_OFF 16384
#define BL_OFF 24576

__device__ __forceinline__ void load_stage(
    const __nv_bfloat16* __restrict__ Ah, const __nv_bfloat16* __restrict__ Al,
    const __nv_bfloat16* __restrict__ Bh, const __nv_bfloat16* __restrict__ Bl,
    unsigned int st, int rBase, int cBase, int kt, int tid)
{
    #pragma unroll
    for (int i = 0; i < 2; i++) {
        int c   = tid * 2 + i;
        int row = c >> 2;
        int kc  = c & 3;
        unsigned int dsw = (unsigned int)(row * 64) +
                           (unsigned int)((kc ^ ((row >> 1) & 3)) << 4);
        size_t aoff = (size_t)(rBase + row) * DD + kt * 32 + kc * 8;
        size_t boff = (size_t)(cBase + row) * DD + kt * 32 + kc * 8;
        cp_async16(st + AH_OFF + dsw, Ah + aoff);
        cp_async16(st + AL_OFF + dsw, Al + aoff);
        cp_async16(st + BH_OFF + dsw, Bh + boff);
        cp_async16(st + BL_OFF + dsw, Bl + boff);
    }
}

template<int MODE>
__global__ __launch_bounds__(256)
void gemm_mma_kernel(const float* __restrict__ bias0,
                     const float* __restrict__ bias1,
                     float* __restrict__ Cout)
{
    extern __shared__ char smem[];
    const unsigned int sb = smem_to_u32(smem);
    const int tid  = threadIdx.x;
    const int lane = tid & 31;
    const int wid  = tid >> 5;
    const int warp_m = wid & 3;
    const int warp_n = wid >> 2;
    const int rBase = blockIdx.x << 7;
    const int cBase = blockIdx.y << 7;
    const int z = blockIdx.z;

    const __nv_bfloat16 *Ah, *Al, *Bh, *Bl;
    const float* bias;
    if (MODE == 0) {
        Ah = g_Ah[0]; Al = g_Al[0]; Bh = g_Wh[2]; Bl = g_Wl[2]; bias = bias0;
    } else {
        Ah = g_Ah[z]; Al = g_Al[z];
        int wi = (z == 2) ? 1 : 0;
        Bh = g_Wh[wi]; Bl = g_Wl[wi];
        bias = (z == 2) ? bias1 : bias0;
    }

    float acc[2][8][4];
    #pragma unroll
    for (int mf = 0; mf < 2; mf++)
        #pragma unroll
        for (int nf = 0; nf < 8; nf++)
            #pragma unroll
            for (int i = 0; i < 4; i++) acc[mf][nf][i] = 0.f;

    load_stage(Ah, Al, Bh, Bl, sb,              rBase, cBase, 0, tid); CP_COMMIT();
    load_stage(Ah, Al, Bh, Bl, sb + STG_STRIDE, rBase, cBase, 1, tid); CP_COMMIT();

    for (int kt = 0; kt < 16; kt++) {
        CP_WAIT1();
        __syncthreads();
        if (kt + 2 < 16)
            load_stage(Ah, Al, Bh, Bl, sb + ((kt + 2) % 3) * STG_STRIDE,
                       rBase, cBase, kt + 2, tid);
        CP_COMMIT();

        const unsigned int stB = sb + (kt % 3) * STG_STRIDE;
        #pragma unroll
        for (int ks = 0; ks < 2; ks++) {
            unsigned int ah[2][4], al[2][4], bh[4][4], bl[4][4];
            #pragma unroll
            for (int mf = 0; mf < 2; mf++) {
                int row = warp_m * 32 + mf * 16 + (lane & 15);
                int kchunk = ks * 2 + (lane >> 4);
                unsigned int ad = stB + (unsigned int)(row * 64) +
                    (unsigned int)((kchunk ^ ((row >> 1) & 3)) << 4);
                ldmatrix_x4(ah[mf], ad + AH_OFF);
                ldmatrix_x4(al[mf], ad + AL_OFF);
            }
            #pragma unroll
            for (int p = 0; p < 4; p++) {
                int row = warp_n * 64 + p * 16 + (lane & 7) + ((lane & 16) >> 1);
                int kchunk = ks * 2 + ((lane >> 3) & 1);
                unsigned int bd = stB + (unsigned int)(row * 64) +
                    (unsigned int)((kchunk ^ ((row >> 1) & 3)) << 4);
                ldmatrix_x4(bh[p], bd + BH_OFF);
                ldmatrix_x4(bl[p], bd + BL_OFF);
            }
            #pragma unroll
            for (int mf = 0; mf < 2; mf++)
                #pragma unroll
                for (int nf = 0; nf < 8; nf++) {
                    int p = nf >> 1, hh = (nf & 1) * 2;
                    mma_bf16(acc[mf][nf], ah[mf], bh[p][hh], bh[p][hh+1]);
                    mma_bf16(acc[mf][nf], ah[mf], bl[p][hh], bl[p][hh+1]);
                    mma_bf16(acc[mf][nf], al[mf], bh[p][hh], bh[p][hh+1]);
                }
        }
    }

    if (MODE == 0) {
        #pragma unroll
        for (int mf = 0; mf < 2; mf++)
            #pragma unroll
            for (int nf = 0; nf < 8; nf++) {
                int col = cBase + warp_n * 64 + nf * 8 + (lane & 3) * 2;
                int row = rBase + warp_m * 32 + mf * 16 + (lane >> 2);
                float b0 = bias[col], b1 = bias[col + 1];
                float2 v0 = make_float2(acc[mf][nf][0] + b0, acc[mf][nf][1] + b1);
                float2 v1 = make_float2(acc[mf][nf][2] + b0, acc[mf][nf][3] + b1);
                *(float2*)(Cout + (size_t)row * DD + col) = v0;
                *(float2*)(Cout + (size_t)(row + 8) * DD + col) = v1;
            }
    } else if (z <= 1) {
        // Q/K: bf16 hi/lo split, [bh][s][df]
        const float scl = (z == 0) ? 0.125f : 1.f;
        __nv_bfloat16* dh = (z == 0) ? g_Qh : g_Kh;
        __nv_bfloat16* dl = (z == 0) ? g_Ql : g_Kl;
        #pragma unroll
        for (int mf = 0; mf < 2; mf++)
            #pragma unroll
            for (int nf = 0; nf < 8; nf++) {
                int col = cBase + warp_n * 64 + nf * 8 + (lane & 3) * 2;
                int row = rBase + warp_m * 32 + mf * 16 + (lane >> 2);
                float b0 = bias[col], b1 = bias[col + 1];
                float x0 = (acc[mf][nf][0] + b0) * scl, y0 = (acc[mf][nf][1] + b1) * scl;
                float x1 = (acc[mf][nf][2] + b0) * scl, y1 = (acc[mf][nf][3] + b1) * scl;
                int h = col >> 6, df = col & 63;
                int b_ = row >> 9, s_ = row & (SS - 1);
                int bh_ = b_ * HH + h;
                size_t i0 = ((size_t)bh_ * SS + s_) * DFF + df;
                size_t i1 = ((size_t)bh_ * SS + s_ + 8) * DFF + df;
                __nv_bfloat16 h00 = __float2bfloat16(x0), h01 = __float2bfloat16(y0);
                __nv_bfloat16 h10 = __float2bfloat16(x1), h11 = __float2bfloat16(y1);
                *(unsigned int*)(dh + i0) =
                    (unsigned int)__bfloat16_as_ushort(h00) |
                    ((unsigned int)__bfloat16_as_ushort(h01) << 16);
                *(unsigned int*)(dh + i1) =
                    (unsigned int)__bfloat16_as_ushort(h10) |
                    ((unsigned int)__bfloat16_as_ushort(h11) << 16);
                *(unsigned int*)(dl + i0) =
                    bfpack(x0 - __bfloat162float(h00), y0 - __bfloat162float(h01));
                *(unsigned int*)(dl + i1) =
                    bfpack(x1 - __bfloat162float(h10), y1 - __bfloat162float(h11));
            }
    } else {
        // V: transpose through SMEM -> [bh][df][s] bf16 hi/lo
        float* SV = (float*)smem;       // 128 cols x (128+4) rows
        __syncthreads();
        #pragma unroll
        for (int mf = 0; mf < 2; mf++)
            #pragma unroll
            for (int nf = 0; nf < 8; nf++) {
                int cl = warp_n * 64 + nf * 8 + (lane & 3) * 2;
                int rl = warp_m * 32 + mf * 16 + (lane >> 2);
                float b0 = bias[cBase + cl], b1 = bias[cBase + cl + 1];
                SV[cl * 132 + rl]       = acc[mf][nf][0] + b0;
                SV[(cl+1) * 132 + rl]   = acc[mf][nf][1] + b1;
                SV[cl * 132 + rl + 8]   = acc[mf][nf][2] + b0;
                SV[(cl+1) * 132 + rl+8] = acc[mf][nf][3] + b1;
            }
        __syncthreads();
        int ldf = tid >> 1;
        int s0  = (tid & 1) * 64;
        int gcol = cBase + ldf;
        int h = gcol >> 6, df = gcol & 63;
        int b_ = rBase >> 9, sBase = rBase & (SS - 1);
        size_t base = (((size_t)(b_ * HH + h) * DFF + df) * SS) + sBase + s0;
        #pragma unroll
        for (int u = 0; u < 64; u += 8) {
            float4 x = *(float4*)&SV[ldf * 132 + s0 + u];
            float4 y = *(float4*)&SV[ldf * 132 + s0 + u + 4];
            float vv[8] = {x.x, x.y, x.z, x.w, y.x, y.y, y.z, y.w};
            unsigned int hw[4], lw[4];
            #pragma unroll
            for (int i = 0; i < 4; i++) {
                __nv_bfloat16 p0 = __float2bfloat16(vv[2*i]);
                __nv_bfloat16 p1 = __float2bfloat16(vv[2*i+1]);
                hw[i] = (unsigned int)__bfloat16_as_ushort(p0) |
                        ((unsigned int)__bfloat16_as_ushort(p1) << 16);
                lw[i] = bfpack(vv[2*i] - __bfloat162float(p0),
                               vv[2*i+1] - __bfloat162float(p1));
            }
            *(uint4*)(g_Vh + base + u) = make_uint4(hw[0], hw[1], hw[2], hw[3]);
            *(uint4*)(g_Vl + base + u) = make_uint4(lw[0], lw[1], lw[2], lw[3]);
        }
    }
}

// ===========================================================================
// Attention: mma QK^T -> fp32 SC -> phase2 (softmax/cumsum/decay/softmax,
// writes P bf16 hi/lo) -> mma PV -> g_CT.  32 q-rows per CTA, 256 threads.
// ===========================================================================
#define AQ_H 0
#define AQ_L 4096
#define ASC  8192
#define AP_H 74240
#define AP_L 107008
#define AOP_H 139776
#define AOP_L 172544
#define ATTN_SMEM_TOT 205312

__global__ __launch_bounds__(256)
void akt_attn_kernel(const float* __restrict__ gammas,
                     const int* __restrict__ zero_pad)
{
    extern __shared__ char smem[];
    const unsigned int sb = smem_to_u32(smem);
    float* SC = (float*)(smem + ASC);
    const int tid = threadIdx.x, lane = tid & 31, wid = tid >> 5;
    const int bh = blockIdx.y, b = bh >> 3, h = bh & 7;
    const int q0 = blockIdx.x << 5, qmax = q0 + 31;
    const int njt = (qmax >> 8) + 1;          // 256-wide j-tiles
    const int wm = wid & 1, wn = wid >> 1;    // 2m x 4n

    const __nv_bfloat16* Qh = g_Qh + ((size_t)bh * SS + q0) * DFF;
    const __nv_bfloat16* Ql = g_Ql + ((size_t)bh * SS + q0) * DFF;
    const __nv_bfloat16* Kh = g_Kh + (size_t)bh * SS * DFF;
    const __nv_bfloat16* Kl = g_Kl + (size_t)bh * SS * DFF;
    const __nv_bfloat16* Vh = g_Vh + (size_t)bh * DFF * SS;
    const __nv_bfloat16* Vl = g_Vl + (size_t)bh * DFF * SS;

    // ---- load Q (32x128B, hi/lo) ----
    {
        int row = tid >> 3, kc = tid & 7;
        unsigned int dsw = (unsigned int)(row * 128) +
                           (unsigned int)((kc ^ (row & 7)) << 4);
        cp_async16(sb + AQ_H + dsw, Qh + row * DFF + kc * 8);
        cp_async16(sb + AQ_L + dsw, Ql + row * DFF + kc * 8);
    }
    // ---- load K tile 0 (256x128B, hi/lo) ----
    #pragma unroll
    for (int u = 0; u < 8; u++) {
        int c = u * 256 + tid;
        int row = c >> 3, kc = c & 7;
        unsigned int dsw = (unsigned int)(row * 128) +
                           (unsigned int)((kc ^ (row & 7)) << 4);
        cp_async16(sb + AOP_H + dsw, Kh + row * DFF + kc * 8);
        cp_async16(sb + AOP_L + dsw, Kl + row * DFF + kc * 8);
    }
    CP_COMMIT();
    CP_WAIT0();
    __syncthreads();

    // ---- Phase 1: scores via mma ----
    for (int jt = 0; jt < njt; jt++) {
        if (jt > 0) {
            __syncthreads();
            #pragma unroll
            for (int u = 0; u < 8; u++) {
                int c = u * 256 + tid;
                int row = c >> 3, kc = c & 7;
                unsigned int dsw = (unsigned int)(row * 128) +
                                   (unsigned int)((kc ^ (row & 7)) << 4);
                cp_async16(sb + AOP_H + dsw, Kh + (jt*256 + row) * DFF + kc * 8);
                cp_async16(sb + AOP_L + dsw, Kl + (jt*256 + row) * DFF + kc * 8);
            }
            CP_COMMIT();
            CP_WAIT0();
            __syncthreads();
        }
        float acc[8][4];
        #pragma unroll
        for (int nf = 0; nf < 8; nf++)
            #pragma unroll
            for (int i = 0; i < 4; i++) acc[nf][i] = 0.f;

        #pragma unroll
        for (int ks = 0; ks < 4; ks++) {
            unsigned int ah[4], al[4], bhf[4][4], blf[4][4];
            {
                int row = wm * 16 + (lane & 15);
                int kc = ks * 2 + (lane >> 4);
                unsigned int ad = sb + (unsigned int)(row * 128) +
                                  (unsigned int)((kc ^ (row & 7)) << 4);
                ldmatrix_x4(ah, ad + AQ_H);
                ldmatrix_x4(al, ad + AQ_L);
            }
            #pragma unroll
            for (int p = 0; p < 4; p++) {
                int row = wn * 64 + p * 16 + (lane & 7) + ((lane & 16) >> 1);
                int kc = ks * 2 + ((lane >> 3) & 1);
                unsigned int bd = sb + (unsigned int)(row * 128) +
                                  (unsigned int)((kc ^ (row & 7)) << 4);
                ldmatrix_x4(bhf[p], bd + AOP_H);
                ldmatrix_x4(blf[p], bd + AOP_L);
            }
            #pragma unroll
            for (int nf = 0; nf < 8; nf++) {
                int p = nf >> 1, hh = (nf & 1) * 2;
                mma_bf16(acc[nf], ah, bhf[p][hh], bhf[p][hh+1]);
                mma_bf16(acc[nf], ah, blf[p][hh], blf[p][hh+1]);
                mma_bf16(acc[nf], al, bhf[p][hh], bhf[p][hh+1]);
            }
        }
        int r0 = wm * 16 + (lane >> 2);
        #pragma unroll
        for (int nf = 0; nf < 8; nf++) {
            int col = jt * 256 + wn * 64 + nf * 8 + (lane & 3) * 2;
            *(float2*)&SC[r0 * SCP + col] = make_float2(acc[nf][0], acc[nf][1]);
            *(float2*)&SC[(r0+8) * SCP + col] = make_float2(acc[nf][2], acc[nf][3]);
        }
    }
    __syncthreads();

    // ---- kick V tile 0 load (OP region free now) ----
    #pragma unroll
    for (int u = 0; u < 8; u++) {
        int c = u * 256 + tid;
        int row = c >> 5, kc = c & 31;
        unsigned int dsw = (unsigned int)(row * 512) +
                           (unsigned int)((kc ^ (row & 7)) << 4);
        cp_async16(sb + AOP_H + dsw, Vh + row * SS + kc * 8);
        cp_async16(sb + AOP_L + dsw, Vl + row * SS + kc * 8);
    }
    CP_COMMIT();

    // ---- Phase 2 ----
    const float gamma = -log1pf(__expf(gammas[h]));
    const int zp = *zero_pad;
    const int nch3 = njt << 3;            // P coverage in 32-chunks
    const int w = wid;

    for (int pass = 0; pass < 4; pass++) {
        const int qr = (pass << 3) + w;
        const int qg = q0 + qr;
        const int qtop = qg >> 5;
        float sv[16], pv[16];

        #pragma unroll
        for (int i = 0; i < 16; i++)
            if (i <= qtop) sv[i] = SC[qr*SCP + (i<<5) + lane];

        float m = -3.0e38f;
        #pragma unroll
        for (int i = 0; i < 16; i++) {
            if (i <= qtop) {
                int j = (i<<5) + lane;
                if (j <= qg) m = fmaxf(m, sv[i]);
            }
        }
        #pragma unroll
        for (int off = 16; off > 0; off >>= 1)
            m = fmaxf(m, __shfl_xor_sync(0xffffffffu, m, off));
        float ssum = 0.f;
        #pragma unroll
        for (int i = 0; i < 16; i++) {
            if (i <= qtop) {
                int j = (i<<5) + lane;
                pv[i] = (j <= qg) ? __expf(sv[i] - m) : 0.f;
                ssum += pv[i];
            }
        }
        #pragma unroll
        for (int off = 16; off > 0; off >>= 1)
            ssum += __shfl_xor_sync(0xffffffffu, ssum, off);
        const float inv1 = 1.f / ssum;

        float carry = 0.f;
        const float* dfrow = g_DF + ((size_t)b * SS + qg) * SS;
        #pragma unroll
        for (int i = 0; i < 16; i++) {
            if (i <= qtop) {
                int j = (i<<5) + lane;
                float s = pv[i] * inv1;
                #pragma unroll
                for (int off = 1; off < 32; off <<= 1) {
                    float t = __shfl_up_sync(0xffffffffu, s, off);
                    if (lane >= off) s += t;
                }
                float tot = __shfl_sync(0xffffffffu, s, 31);
                float c = carry + s;
                carry += tot;
                float rem = fmaxf(1.f - c, 0.f);
                float dsc = (j <= qg) ? sqrtf(rem * (float)(qg - j)) : 0.f;
                float te = __expf(dsc * gamma * dfrow[j]);
                te = fminf(fmaxf(te, 1e-5f), 1e5f);
                pv[i] = (j <= qg) ? sv[i] * te : -3.0e38f;
            }
        }

        float m2 = -3.0e38f;
        #pragma unroll
        for (int i = 0; i < 16; i++)
            if (i <= qtop) m2 = fmaxf(m2, pv[i]);
        #pragma unroll
        for (int off = 16; off > 0; off >>= 1)
            m2 = fmaxf(m2, __shfl_xor_sync(0xffffffffu, m2, off));
        float sum2 = 0.f;
        #pragma unroll
        for (int i = 0; i < 16; i++) {
            if (i <= qtop) {
                int j = (i<<5) + lane;
                float e = (j <= qg) ? __expf(pv[i] - m2) : 0.f;
                sv[i] = e;
                sum2 += e;
            }
        }
        #pragma unroll
        for (int off = 16; off > 0; off >>= 1)
            sum2 += __shfl_xor_sync(0xffffffffu, sum2, off);
        const float inv2 = 1.f / sum2;
        const bool zrow = (zp != 0) && (qg == 0);

        // write P (bf16 hi/lo) into swizzled A-operand layout
        #pragma unroll
        for (int i = 0; i < 16; i++) {
            if (i < nch3) {
                int j = (i<<5) + lane;
                float pr = (i <= qtop && !zrow) ? sv[i] * inv2 : 0.f;
                __nv_bfloat16 ph = __float2bfloat16(pr);
                __nv_bfloat16 pl = __float2bfloat16(pr - __bfloat162float(ph));
                int kc = j >> 3;
                unsigned int off2 = (unsigned int)(qr * 1024) +
                                    (unsigned int)((kc ^ (qr & 7)) << 4) +
                                    (unsigned int)((j & 7) << 1);
                *(__nv_bfloat16*)(smem + AP_H + off2) = ph;
                *(__nv_bfloat16*)(smem + AP_L + off2) = pl;
            }
        }
    }

    CP_WAIT0();
    __syncthreads();   // P written by all warps, V tile 0 ready

    // ---- Phase 3: out = P @ V via mma ----
    float oacc[2][4];
    #pragma unroll
    for (int nf = 0; nf < 2; nf++)
        #pragma unroll
        for (int i = 0; i < 4; i++) oacc[nf][i] = 0.f;

    for (int jt = 0; jt < njt; jt++) {
        if (jt > 0) {
            __syncthreads();
            #pragma unroll
            for (int u = 0; u < 8; u++) {
                int c = u * 256 + tid;
                int row = c >> 5, kc = c & 31;
                unsigned int dsw = (unsigned int)(row * 512) +
                                   (unsigned int)((kc ^ (row & 7)) << 4);
                cp_async16(sb + AOP_H + dsw, Vh + row * SS + jt*256 + kc * 8);
                cp_async16(sb + AOP_L + dsw, Vl + row * SS + jt*256 + kc * 8);
            }
            CP_COMMIT();
            CP_WAIT0();
            __syncthreads();
        }
        #pragma unroll 4
        for (int ks = 0; ks < 16; ks++) {
            unsigned int ph[4], pl[4], vh[4], vl[4];
            {
                int row = wm * 16 + (lane & 15);
                int kc = jt * 32 + ks * 2 + (lane >> 4);
                unsigned int ad = sb + (unsigned int)(row * 1024) +
                                  (unsigned int)((kc ^ (row & 7)) << 4);
                ldmatrix_x4(ph, ad + AP_H);
                ldmatrix_x4(pl, ad + AP_L);
            }
            {
                int row = wn * 16 + (lane & 7) + ((lane & 16) >> 1);
                int kc = ks * 2 + ((lane >> 3) & 1);
                unsigned int bd = sb + (unsigned int)(row * 512) +
                                  (unsigned int)((kc ^ (row & 7)) << 4);
                ldmatrix_x4(vh, bd + AOP_H);
                ldmatrix_x4(vl, bd + AOP_L);
            }
            #pragma unroll
            for (int nf = 0; nf < 2; nf++) {
                int hh = nf * 2;
                mma_bf16(oacc[nf], ph, vh[hh], vh[hh+1]);
                mma_bf16(oacc[nf], pl, vh[hh], vh[hh+1]);
                mma_bf16(oacc[nf], ph, vl[hh], vl[hh+1]);
            }
        }
    }

    // epilogue -> g_CT
    {
        int row = q0 + wm * 16 + (lane >> 2);
        #pragma unroll
        for (int nf = 0; nf < 2; nf++) {
            int col = h * 64 + wn * 16 + nf * 8 + (lane & 3) * 2;
            *(float2*)(g_CT + ((size_t)(b * SS + row) * DD) + col) =
                make_float2(oacc[nf][0], oacc[nf][1]);
            *(float2*)(g_CT + ((size_t)(b * SS + row + 8) * DD) + col) =
                make_float2(oacc[nf][2], oacc[nf][3]);
        }
    }
}

// ---------------------------------------------------------------------------
extern "C" void kernel_launch(void* const* d_in, const int* in_sizes, int n_in,
                              void* d_out, int out_size)
{
    const float* q      = (const float*)d_in[0];
    const float* k      = (const float*)d_in[1];
    const float* v      = (const float*)d_in[2];
    const int*   zero_pad = (const int*)d_in[4];
    const float* qd     = (const float*)d_in[5];
    const float* Wk     = (const float*)d_in[6];
    const float* bk     = (const float*)d_in[7];
    const float* Wv     = (const float*)d_in[8];
    const float* bv     = (const float*)d_in[9];
    const float* Wo     = (const float*)d_in[10];
    const float* bo     = (const float*)d_in[11];
    const float* gammas = (const float*)d_in[12];
    float* out = (float*)d_out;

    const int GEMM_SMEM = 3 * STG_STRIDE;    // 98304 B
    cudaFuncSetAttribute(gemm_mma_kernel<1>,
                         cudaFuncAttributeMaxDynamicSharedMemorySize, GEMM_SMEM);
    cudaFuncSetAttribute(gemm_mma_kernel<0>,
                         cudaFuncAttributeMaxDynamicSharedMemorySize, GEMM_SMEM);
    cudaFuncSetAttribute(akt_attn_kernel,
                         cudaFuncAttributeMaxDynamicSharedMemorySize, ATTN_SMEM_TOT);

    const int N_IN = BB * SS * DD;
    const int N_QD = BB * SS * SS;
    const int N_W  = DD * DD;

    convert_split<<<N_IN / 2048, 256>>>(q,  0, N_IN);
    convert_split<<<N_IN / 2048, 256>>>(k,  1, N_IN);
    convert_split<<<N_IN / 2048, 256>>>(v,  2, N_IN);
    convert_split<<<N_W  / 2048, 256>>>(Wk, 3, N_W);
    convert_split<<<N_W  / 2048, 256>>>(Wv, 4, N_W);
    convert_split<<<N_W  / 2048, 256>>>(Wo, 5, N_W);
    diff_kernel<<<N_QD / 1024, 256>>>(qd);

    gemm_mma_kernel<1><<<dim3(128, 4, 3), 256, GEMM_SMEM>>>(bk, bv, nullptr);

    akt_attn_kernel<<<dim3(16, 256), 256, ATTN_SMEM_TOT>>>(gammas, zero_pad);

    convert_split<<<N_IN / 2048, 256>>>(nullptr, 6, N_IN);

    gemm_mma_kernel<0><<<dim3(128, 4, 1), 256, GEMM_SMEM>>>(bo, nullptr, out);
}

// round 14
// speedup vs baseline: 1.2753x; 1.2753x over previous
#include <cuda_runtime.h>
#include <cuda_bf16.h>
#include <stdint.h>
#include <math.h>

#define BB 32
#define SS 512
#define DD 512
#define HH 8
#define DFF 64

// Scratch (allocation-free)
__device__ float g_CT[BB*SS*DD];
__device__ float g_DF[BB*SS*SS];      // exp(sigmoid(qd)) precomputed

// bf16 hi/lo split operand buffers (GEMM inputs)
__device__ __nv_bfloat16 g_Ah[3][BB*SS*DD];
__device__ __nv_bfloat16 g_Al[3][BB*SS*DD];
__device__ __nv_bfloat16 g_Wh[3][DD*DD];
__device__ __nv_bfloat16 g_Wl[3][DD*DD];

// attention operands (written by projection epilogue)
__device__ __nv_bfloat16 g_Qh[BB*HH*SS*DFF];   // [bh][s][df], pre-scaled 1/8
__device__ __nv_bfloat16 g_Ql[BB*HH*SS*DFF];
__device__ __nv_bfloat16 g_Kh[BB*HH*SS*DFF];   // [bh][s][df]
__device__ __nv_bfloat16 g_Kl[BB*HH*SS*DFF];
__device__ __nv_bfloat16 g_Vh[BB*HH*DFF*SS];   // [bh][df][s]  (transposed)
__device__ __nv_bfloat16 g_Vl[BB*HH*DFF*SS];

// ===========================================================================
// PTX helpers (portable sm_80+ subset)
// ===========================================================================
__device__ __forceinline__ unsigned int smem_to_u32(const void* p) {
    unsigned int a;
    asm("{ .reg .u64 t; cvta.to.shared.u64 t, %1; cvt.u32.u64 %0, t; }"
        : "=r"(a) : "l"(p));
    return a;
}

__device__ __forceinline__ void cp_async16(unsigned int dst, const void* src) {
    asm volatile("cp.async.cg.shared.global [%0], [%1], 16;\n"
                 :: "r"(dst), "l"(src));
}
#define CP_COMMIT() asm volatile("cp.async.commit_group;\n" ::: "memory")
#define CP_WAIT1()  asm volatile("cp.async.wait_group 1;\n" ::: "memory")
#define CP_WAIT0()  asm volatile("cp.async.wait_group 0;\n" ::: "memory")

__device__ __forceinline__ void ldmatrix_x4(unsigned int* r, unsigned int addr) {
    asm volatile("ldmatrix.sync.aligned.m8n8.x4.shared.b16 {%0,%1,%2,%3}, [%4];"
                 : "=r"(r[0]), "=r"(r[1]), "=r"(r[2]), "=r"(r[3]) : "r"(addr));
}

__device__ __forceinline__ void mma_bf16(float* c, const unsigned int* a,
                                         unsigned int b0, unsigned int b1) {
    asm volatile(
        "mma.sync.aligned.m16n8k16.row.col.f32.bf16.bf16.f32 "
        "{%0,%1,%2,%3}, {%4,%5,%6,%7}, {%8,%9}, {%0,%1,%2,%3};"
        : "+f"(c[0]), "+f"(c[1]), "+f"(c[2]), "+f"(c[3])
        : "r"(a[0]), "r"(a[1]), "r"(a[2]), "r"(a[3]), "r"(b0), "r"(b1));
}

__device__ __forceinline__ unsigned int bfpack(float x, float y) {
    __nv_bfloat16 h0 = __float2bfloat16(x), h1 = __float2bfloat16(y);
    return (unsigned int)__bfloat16_as_ushort(h0) |
           ((unsigned int)__bfloat16_as_ushort(h1) << 16);
}

// ===========================================================================
// Precompute diff = exp(sigmoid(qd))
// ===========================================================================
__global__ __launch_bounds__(256)
void diff_kernel(const float* __restrict__ qd)
{
    int idx = (blockIdx.x * 256 + threadIdx.x) << 2;
    float4 a = *(const float4*)(qd + idx);
    float4 o;
    o.x = __expf(1.f / (1.f + __expf(-a.x)));
    o.y = __expf(1.f / (1.f + __expf(-a.y)));
    o.z = __expf(1.f / (1.f + __expf(-a.z)));
    o.w = __expf(1.f / (1.f + __expf(-a.w)));
    *(float4*)(g_DF + idx) = o;
}

// ===========================================================================
// Convert fp32 -> bf16 hi/lo split.  which: 0-2 inputs, 3-5 weights, 6: g_CT
// ===========================================================================
__global__ __launch_bounds__(256)
void convert_split(const float* __restrict__ src_in, int which, int n)
{
    const float* src = (which == 6) ? g_CT : src_in;
    __nv_bfloat16 *hi, *lo;
    if (which < 3)      { hi = g_Ah[which];   lo = g_Al[which]; }
    else if (which < 6) { hi = g_Wh[which-3]; lo = g_Wl[which-3]; }
    else                { hi = g_Ah[0];       lo = g_Al[0]; }

    int idx = (blockIdx.x * 256 + threadIdx.x) << 3;
    if (idx >= n) return;
    float4 a = *(const float4*)(src + idx);
    float4 b = *(const float4*)(src + idx + 4);
    float v[8] = {a.x, a.y, a.z, a.w, b.x, b.y, b.z, b.w};
    unsigned int hw[4], lw[4];
    #pragma unroll
    for (int i = 0; i < 4; i++) {
        float x = v[2*i], y = v[2*i+1];
        __nv_bfloat16 h0 = __float2bfloat16(x), h1 = __float2bfloat16(y);
        float r0 = x - __bfloat162float(h0), r1 = y - __bfloat162float(h1);
        hw[i] = (unsigned int)__bfloat16_as_ushort(h0) |
                ((unsigned int)__bfloat16_as_ushort(h1) << 16);
        lw[i] = bfpack(r0, r1);
    }
    *(uint4*)(hi + idx) = make_uint4(hw[0], hw[1], hw[2], hw[3]);
    *(uint4*)(lo + idx) = make_uint4(lw[0], lw[1], lw[2], lw[3]);
}

// ===========================================================================
// mma.sync bf16 3-term split GEMM.  Tile 128x128, BK=32, 3-stage cp.async.
// MODE 0: C -> Cout (fp32 row-major).  MODE 1: z=0/1 -> g_Qh/l,g_Kh/l
// ([bh][s][df], Q scaled 1/8); z=2 -> g_Vh/l transposed [bh][df][s].
// ===========================================================================
#define STG_STRIDE 32768
#define AH_OFF 0
#define AL_OFF 8192
#define BH_OFF 16384
#define BL_OFF 24576

__device__ __forceinline__ void load_stage(
    const __nv_bfloat16* __restrict__ Ah, const __nv_bfloat16* __restrict__ Al,
    const __nv_bfloat16* __restrict__ Bh, const __nv_bfloat16* __restrict__ Bl,
    unsigned int st, int rBase, int cBase, int kt, int tid)
{
    #pragma unroll
    for (int i = 0; i < 2; i++) {
        int c   = tid * 2 + i;
        int row = c >> 2;
        int kc  = c & 3;
        unsigned int dsw = (unsigned int)(row * 64) +
                           (unsigned int)((kc ^ ((row >> 1) & 3)) << 4);
        size_t aoff = (size_t)(rBase + row) * DD + kt * 32 + kc * 8;
        size_t boff = (size_t)(cBase + row) * DD + kt * 32 + kc * 8;
        cp_async16(st + AH_OFF + dsw, Ah + aoff);
        cp_async16(st + AL_OFF + dsw, Al + aoff);
        cp_async16(st + BH_OFF + dsw, Bh + boff);
        cp_async16(st + BL_OFF + dsw, Bl + boff);
    }
}

template<int MODE>
__global__ __launch_bounds__(256)
void gemm_mma_kernel(const float* __restrict__ bias0,
                     const float* __restrict__ bias1,
                     float* __restrict__ Cout)
{
    extern __shared__ char smem[];
    const unsigned int sb = smem_to_u32(smem);
    const int tid  = threadIdx.x;
    const int lane = tid & 31;
    const int wid  = tid >> 5;
    const int warp_m = wid & 3;
    const int warp_n = wid >> 2;
    const int rBase = blockIdx.x << 7;
    const int cBase = blockIdx.y << 7;
    const int z = blockIdx.z;

    const __nv_bfloat16 *Ah, *Al, *Bh, *Bl;
    const float* bias;
    if (MODE == 0) {
        Ah = g_Ah[0]; Al = g_Al[0]; Bh = g_Wh[2]; Bl = g_Wl[2]; bias = bias0;
    } else {
        Ah = g_Ah[z]; Al = g_Al[z];
        int wi = (z == 2) ? 1 : 0;
        Bh = g_Wh[wi]; Bl = g_Wl[wi];
        bias = (z == 2) ? bias1 : bias0;
    }

    float acc[2][8][4];
    #pragma unroll
    for (int mf = 0; mf < 2; mf++)
        #pragma unroll
        for (int nf = 0; nf < 8; nf++)
            #pragma unroll
            for (int i = 0; i < 4; i++) acc[mf][nf][i] = 0.f;

    load_stage(Ah, Al, Bh, Bl, sb,              rBase, cBase, 0, tid); CP_COMMIT();
    load_stage(Ah, Al, Bh, Bl, sb + STG_STRIDE, rBase, cBase, 1, tid); CP_COMMIT();

    for (int kt = 0; kt < 16; kt++) {
        CP_WAIT1();
        __syncthreads();
        if (kt + 2 < 16)
            load_stage(Ah, Al, Bh, Bl, sb + ((kt + 2) % 3) * STG_STRIDE,
                       rBase, cBase, kt + 2, tid);
        CP_COMMIT();

        const unsigned int stB = sb + (kt % 3) * STG_STRIDE;
        #pragma unroll
        for (int ks = 0; ks < 2; ks++) {
            unsigned int ah[2][4], al[2][4], bh[4][4], bl[4][4];
            #pragma unroll
            for (int mf = 0; mf < 2; mf++) {
                int row = warp_m * 32 + mf * 16 + (lane & 15);
                int kchunk = ks * 2 + (lane >> 4);
                unsigned int ad = stB + (unsigned int)(row * 64) +
                    (unsigned int)((kchunk ^ ((row >> 1) & 3)) << 4);
                ldmatrix_x4(ah[mf], ad + AH_OFF);
                ldmatrix_x4(al[mf], ad + AL_OFF);
            }
            #pragma unroll
            for (int p = 0; p < 4; p++) {
                int row = warp_n * 64 + p * 16 + (lane & 7) + ((lane & 16) >> 1);
                int kchunk = ks * 2 + ((lane >> 3) & 1);
                unsigned int bd = stB + (unsigned int)(row * 64) +
                    (unsigned int)((kchunk ^ ((row >> 1) & 3)) << 4);
                ldmatrix_x4(bh[p], bd + BH_OFF);
                ldmatrix_x4(bl[p], bd + BL_OFF);
            }
            #pragma unroll
            for (int mf = 0; mf < 2; mf++)
                #pragma unroll
                for (int nf = 0; nf < 8; nf++) {
                    int p = nf >> 1, hh = (nf & 1) * 2;
                    mma_bf16(acc[mf][nf], ah[mf], bh[p][hh], bh[p][hh+1]);
                    mma_bf16(acc[mf][nf], ah[mf], bl[p][hh], bl[p][hh+1]);
                    mma_bf16(acc[mf][nf], al[mf], bh[p][hh], bh[p][hh+1]);
                }
        }
    }

    if (MODE == 0) {
        #pragma unroll
        for (int mf = 0; mf < 2; mf++)
            #pragma unroll
            for (int nf = 0; nf < 8; nf++) {
                int col = cBase + warp_n * 64 + nf * 8 + (lane & 3) * 2;
                int row = rBase + warp_m * 32 + mf * 16 + (lane >> 2);
                float b0 = bias[col], b1 = bias[col + 1];
                float2 v0 = make_float2(acc[mf][nf][0] + b0, acc[mf][nf][1] + b1);
                float2 v1 = make_float2(acc[mf][nf][2] + b0, acc[mf][nf][3] + b1);
                *(float2*)(Cout + (size_t)row * DD + col) = v0;
                *(float2*)(Cout + (size_t)(row + 8) * DD + col) = v1;
            }
    } else if (z <= 1) {
        const float scl = (z == 0) ? 0.125f : 1.f;
        __nv_bfloat16* dh = (z == 0) ? g_Qh : g_Kh;
        __nv_bfloat16* dl = (z == 0) ? g_Ql : g_Kl;
        #pragma unroll
        for (int mf = 0; mf < 2; mf++)
            #pragma unroll
            for (int nf = 0; nf < 8; nf++) {
                int col = cBase + warp_n * 64 + nf * 8 + (lane & 3) * 2;
                int row = rBase + warp_m * 32 + mf * 16 + (lane >> 2);
                float b0 = bias[col], b1 = bias[col + 1];
                float x0 = (acc[mf][nf][0] + b0) * scl, y0 = (acc[mf][nf][1] + b1) * scl;
                float x1 = (acc[mf][nf][2] + b0) * scl, y1 = (acc[mf][nf][3] + b1) * scl;
                int h = col >> 6, df = col & 63;
                int b_ = row >> 9, s_ = row & (SS - 1);
                int bh_ = b_ * HH + h;
                size_t i0 = ((size_t)bh_ * SS + s_) * DFF + df;
                size_t i1 = ((size_t)bh_ * SS + s_ + 8) * DFF + df;
                __nv_bfloat16 h00 = __float2bfloat16(x0), h01 = __float2bfloat16(y0);
                __nv_bfloat16 h10 = __float2bfloat16(x1), h11 = __float2bfloat16(y1);
                *(unsigned int*)(dh + i0) =
                    (unsigned int)__bfloat16_as_ushort(h00) |
                    ((unsigned int)__bfloat16_as_ushort(h01) << 16);
                *(unsigned int*)(dh + i1) =
                    (unsigned int)__bfloat16_as_ushort(h10) |
                    ((unsigned int)__bfloat16_as_ushort(h11) << 16);
                *(unsigned int*)(dl + i0) =
                    bfpack(x0 - __bfloat162float(h00), y0 - __bfloat162float(h01));
                *(unsigned int*)(dl + i1) =
                    bfpack(x1 - __bfloat162float(h10), y1 - __bfloat162float(h11));
            }
    } else {
        float* SV = (float*)smem;       // 128 cols x 132 rows
        __syncthreads();
        #pragma unroll
        for (int mf = 0; mf < 2; mf++)
            #pragma unroll
            for (int nf = 0; nf < 8; nf++) {
                int cl = warp_n * 64 + nf * 8 + (lane & 3) * 2;
                int rl = warp_m * 32 + mf * 16 + (lane >> 2);
                float b0 = bias[cBase + cl], b1 = bias[cBase + cl + 1];
                SV[cl * 132 + rl]       = acc[mf][nf][0] + b0;
                SV[(cl+1) * 132 + rl]   = acc[mf][nf][1] + b1;
                SV[cl * 132 + rl + 8]   = acc[mf][nf][2] + b0;
                SV[(cl+1) * 132 + rl+8] = acc[mf][nf][3] + b1;
            }
        __syncthreads();
        int ldf = tid >> 1;
        int s0  = (tid & 1) * 64;
        int gcol = cBase + ldf;
        int h = gcol >> 6, df = gcol & 63;
        int b_ = rBase >> 9, sBase = rBase & (SS - 1);
        size_t base = (((size_t)(b_ * HH + h) * DFF + df) * SS) + sBase + s0;
        #pragma unroll
        for (int u = 0; u < 64; u += 8) {
            float4 x = *(float4*)&SV[ldf * 132 + s0 + u];
            float4 y = *(float4*)&SV[ldf * 132 + s0 + u + 4];
            float vv[8] = {x.x, x.y, x.z, x.w, y.x, y.y, y.z, y.w};
            unsigned int hw[4], lw[4];
            #pragma unroll
            for (int i = 0; i < 4; i++) {
                __nv_bfloat16 p0 = __float2bfloat16(vv[2*i]);
                __nv_bfloat16 p1 = __float2bfloat16(vv[2*i+1]);
                hw[i] = (unsigned int)__bfloat16_as_ushort(p0) |
                        ((unsigned int)__bfloat16_as_ushort(p1) << 16);
                lw[i] = bfpack(vv[2*i] - __bfloat162float(p0),
                               vv[2*i+1] - __bfloat162float(p1));
            }
            *(uint4*)(g_Vh + base + u) = make_uint4(hw[0], hw[1], hw[2], hw[3]);
            *(uint4*)(g_Vl + base + u) = make_uint4(lw[0], lw[1], lw[2], lw[3]);
        }
    }
}

// ===========================================================================
// Attention: 64 q-rows per CTA, 512 threads (16 warps, 4m x 4n).
// SC region rows stride 2176B (swizzled fp32); P bf16 hi/lo aliased onto it.
// ===========================================================================
#define AQ_H 0
#define AQ_L 8192
#define ASC  16384
#define SCR  2176              // row stride bytes (17*128)
#define AOP_H 155648
#define AOP_L 188416
#define ATTN_SMEM_TOT 221184

__global__ __launch_bounds__(512)
void akt_attn_kernel(const float* __restrict__ gammas,
                     const int* __restrict__ zero_pad)
{
    extern __shared__ char smem[];
    const unsigned int sb = smem_to_u32(smem);
    const int tid = threadIdx.x, lane = tid & 31, wid = tid >> 5;
    const int bh = blockIdx.y, b = bh >> 3, h = bh & 7;
    const int q0 = blockIdx.x << 6, qmax = q0 + 63;
    const int njt = (qmax >> 8) + 1;          // 256-wide j-tiles
    const int wm = wid & 3, wn = wid >> 2;    // 4m x 4n

    const __nv_bfloat16* Qh = g_Qh + ((size_t)bh * SS + q0) * DFF;
    const __nv_bfloat16* Ql = g_Ql + ((size_t)bh * SS + q0) * DFF;
    const __nv_bfloat16* Kh = g_Kh + (size_t)bh * SS * DFF;
    const __nv_bfloat16* Kl = g_Kl + (size_t)bh * SS * DFF;
    const __nv_bfloat16* Vh = g_Vh + (size_t)bh * DFF * SS;
    const __nv_bfloat16* Vl = g_Vl + (size_t)bh * DFF * SS;

    // ---- load Q (64x128B hi/lo) ----
    {
        int row = tid >> 3, kc = tid & 7;
        unsigned int dsw = (unsigned int)(row * 128) +
                           (unsigned int)((kc ^ (row & 7)) << 4);
        cp_async16(sb + AQ_H + dsw, Qh + row * DFF + kc * 8);
        cp_async16(sb + AQ_L + dsw, Ql + row * DFF + kc * 8);
    }
    // ---- K tile 0 (256 rows) ----
    #pragma unroll
    for (int u = 0; u < 4; u++) {
        int c = u * 512 + tid;
        int row = c >> 3, kc = c & 7;
        unsigned int dsw = (unsigned int)(row * 128) +
                           (unsigned int)((kc ^ (row & 7)) << 4);
        cp_async16(sb + AOP_H + dsw, Kh + row * DFF + kc * 8);
        cp_async16(sb + AOP_L + dsw, Kl + row * DFF + kc * 8);
    }
    CP_COMMIT();
    CP_WAIT0();
    __syncthreads();

    // ---- Phase 1: scores via mma -> swizzled SC ----
    for (int jt = 0; jt < njt; jt++) {
        if (jt > 0) {
            __syncthreads();
            #pragma unroll
            for (int u = 0; u < 4; u++) {
                int c = u * 512 + tid;
                int row = c >> 3, kc = c & 7;
                unsigned int dsw = (unsigned int)(row * 128) +
                                   (unsigned int)((kc ^ (row & 7)) << 4);
                cp_async16(sb + AOP_H + dsw, Kh + (jt*256 + row) * DFF + kc * 8);
                cp_async16(sb + AOP_L + dsw, Kl + (jt*256 + row) * DFF + kc * 8);
            }
            CP_COMMIT();
            CP_WAIT0();
            __syncthreads();
        }
        float acc[8][4];
        #pragma unroll
        for (int nf = 0; nf < 8; nf++)
            #pragma unroll
            for (int i = 0; i < 4; i++) acc[nf][i] = 0.f;

        #pragma unroll
        for (int ks = 0; ks < 4; ks++) {
            unsigned int ah[4], al[4], bhf[4][4], blf[4][4];
            {
                int row = wm * 16 + (lane & 15);
                int kc = ks * 2 + (lane >> 4);
                unsigned int ad = sb + (unsigned int)(row * 128) +
                                  (unsigned int)((kc ^ (row & 7)) << 4);
                ldmatrix_x4(ah, ad + AQ_H);
                ldmatrix_x4(al, ad + AQ_L);
            }
            #pragma unroll
            for (int p = 0; p < 4; p++) {
                int row = wn * 64 + p * 16 + (lane & 7) + ((lane & 16) >> 1);
                int kc = ks * 2 + ((lane >> 3) & 1);
                unsigned int bd = sb + AOP_H + (unsigned int)(row * 128) +
                                  (unsigned int)((kc ^ (row & 7)) << 4);
                ldmatrix_x4(bhf[p], bd);
                ldmatrix_x4(blf[p], bd + (AOP_L - AOP_H));
            }
            #pragma unroll
            for (int nf = 0; nf < 8; nf++) {
                int p = nf >> 1, hh = (nf & 1) * 2;
                mma_bf16(acc[nf], ah, bhf[p][hh], bhf[p][hh+1]);
                mma_bf16(acc[nf], ah, blf[p][hh], blf[p][hh+1]);
                mma_bf16(acc[nf], al, bhf[p][hh], bhf[p][hh+1]);
            }
        }
        int r0 = wm * 16 + (lane >> 2);
        #pragma unroll
        for (int nf = 0; nf < 8; nf++) {
            int col = jt * 256 + wn * 64 + nf * 8 + (lane & 3) * 2;
            unsigned int o0 = (unsigned int)(r0 * SCR) +
                (unsigned int)((((col >> 2) ^ (r0 & 7)) << 4) + (col & 3) * 4);
            unsigned int o1 = o0 + 8 * SCR;
            *(float2*)(smem + ASC + o0) = make_float2(acc[nf][0], acc[nf][1]);
            *(float2*)(smem + ASC + o1) = make_float2(acc[nf][2], acc[nf][3]);
        }
    }
    __syncthreads();

    // ---- kick V tile 0 load ----
    #pragma unroll
    for (int u = 0; u < 4; u++) {
        int c = u * 512 + tid;
        int row = c >> 5, kc = c & 31;
        unsigned int dsw = (unsigned int)(row * 512) +
                           (unsigned int)((kc ^ (row & 7)) << 4);
        cp_async16(sb + AOP_H + dsw, Vh + row * SS + kc * 8);
        cp_async16(sb + AOP_L + dsw, Vl + row * SS + kc * 8);
    }
    CP_COMMIT();

    // ---- Phase 2 ----
    const float gamma = -log1pf(__expf(gammas[h]));
    const int zp = *zero_pad;
    const int nch3 = njt << 3;

    for (int pass = 0; pass < 4; pass++) {
        const int qr = (pass << 4) + wid;    // 16 warps x 4 passes = 64 rows
        const int qg = q0 + qr;
        const int qtop = qg >> 5;
        const unsigned int rbase = (unsigned int)(qr * SCR);
        float sv[16], pv[16], tot[16];

        #pragma unroll
        for (int i = 0; i < 16; i++) {
            if (i <= qtop) {
                int j = (i << 5) + lane;
                unsigned int off = ((((j >> 2) ^ (qr & 7)) << 4) + (j & 3) * 4);
                sv[i] = *(float*)(smem + ASC + rbase + off);
            }
        }

        float m = -3.0e38f;
        #pragma unroll
        for (int i = 0; i < 16; i++) {
            if (i <= qtop) {
                int j = (i << 5) + lane;
                if (j <= qg) m = fmaxf(m, sv[i]);
            }
        }
        #pragma unroll
        for (int off = 16; off > 0; off >>= 1)
            m = fmaxf(m, __shfl_xor_sync(0xffffffffu, m, off));
        float ssum = 0.f;
        #pragma unroll
        for (int i = 0; i < 16; i++) {
            if (i <= qtop) {
                int j = (i << 5) + lane;
                pv[i] = (j <= qg) ? __expf(sv[i] - m) : 0.f;
                ssum += pv[i];
            }
        }
        #pragma unroll
        for (int off = 16; off > 0; off >>= 1)
            ssum += __shfl_xor_sync(0xffffffffu, ssum, off);
        const float inv1 = 1.f / ssum;

        // independent chunk-local scans (no cross-chunk dependency)
        #pragma unroll
        for (int i = 0; i < 16; i++) {
            if (i <= qtop) {
                float s = pv[i] * inv1;
                #pragma unroll
                for (int off = 1; off < 32; off <<= 1) {
                    float t = __shfl_up_sync(0xffffffffu, s, off);
                    if (lane >= off) s += t;
                }
                pv[i] = s;
                tot[i] = __shfl_sync(0xffffffffu, s, 31);
            }
        }
        // cheap register prefix over chunk totals + decay
        const float* dfrow = g_DF + ((size_t)b * SS + qg) * SS;
        float pre = 0.f;
        #pragma unroll
        for (int i = 0; i < 16; i++) {
            if (i <= qtop) {
                int j = (i << 5) + lane;
                float c = pre + pv[i];
                pre += tot[i];
                float rem = fmaxf(1.f - c, 0.f);
                float dsc = (j <= qg) ? sqrtf(rem * (float)(qg - j)) : 0.f;
                float te = __expf(dsc * gamma * dfrow[j]);
                te = fminf(fmaxf(te, 1e-5f), 1e5f);
                pv[i] = (j <= qg) ? sv[i] * te : -3.0e38f;
            }
        }

        float m2 = -3.0e38f;
        #pragma unroll
        for (int i = 0; i < 16; i++)
            if (i <= qtop) m2 = fmaxf(m2, pv[i]);
        #pragma unroll
        for (int off = 16; off > 0; off >>= 1)
            m2 = fmaxf(m2, __shfl_xor_sync(0xffffffffu, m2, off));
        float sum2 = 0.f;
        #pragma unroll
        for (int i = 0; i < 16; i++) {
            if (i <= qtop) {
                int j = (i << 5) + lane;
                float e = (j <= qg) ? __expf(pv[i] - m2) : 0.f;
                sv[i] = e;
                sum2 += e;
            }
        }
        #pragma unroll
        for (int off = 16; off > 0; off >>= 1)
            sum2 += __shfl_xor_sync(0xffffffffu, sum2, off);
        const float inv2 = 1.f / sum2;
        const bool zrow = (zp != 0) && (qg == 0);

        // write P (bf16 hi/lo) aliased onto this row's SC bytes
        #pragma unroll
        for (int i = 0; i < 16; i++) {
            if (i < nch3) {
                int j = (i << 5) + lane;
                float pr = (i <= qtop && !zrow) ? sv[i] * inv2 : 0.f;
                __nv_bfloat16 ph = __float2bfloat16(pr);
                __nv_bfloat16 pl = __float2bfloat16(pr - __bfloat162float(ph));
                unsigned int off2 = (unsigned int)((((j >> 3) ^ (qr & 7)) << 4) +
                                                   ((j & 7) << 1));
                *(__nv_bfloat16*)(smem + ASC + rbase + off2) = ph;
                *(__nv_bfloat16*)(smem + ASC + rbase + 1024 + off2) = pl;
            }
        }
    }

    CP_WAIT0();
    __syncthreads();   // all P written, V tile 0 ready

    // ---- Phase 3: out = P @ V via mma ----
    float oacc[2][4];
    #pragma unroll
    for (int nf = 0; nf < 2; nf++)
        #pragma unroll
        for (int i = 0; i < 4; i++) oacc[nf][i] = 0.f;

    for (int jt = 0; jt < njt; jt++) {
        if (jt > 0) {
            __syncthreads();
            #pragma unroll
            for (int u = 0; u < 4; u++) {
                int c = u * 512 + tid;
                int row = c >> 5, kc = c & 31;
                unsigned int dsw = (unsigned int)(row * 512) +
                                   (unsigned int)((kc ^ (row & 7)) << 4);
                cp_async16(sb + AOP_H + dsw, Vh + row * SS + jt*256 + kc * 8);
                cp_async16(sb + AOP_L + dsw, Vl + row * SS + jt*256 + kc * 8);
            }
            CP_COMMIT();
            CP_WAIT0();
            __syncthreads();
        }
        #pragma unroll 4
        for (int ks = 0; ks < 16; ks++) {
            unsigned int ph[4], pl[4], vh[4], vl[4];
            {
                int row = wm * 16 + (lane & 15);
                int kc = jt * 32 + ks * 2 + (lane >> 4);
                unsigned int ad = sb + ASC + (unsigned int)(row * SCR) +
                                  (unsigned int)((kc ^ (row & 7)) << 4);
                ldmatrix_x4(ph, ad);
                ldmatrix_x4(pl, ad + 1024);
            }
            {
                int row = wn * 16 + (lane & 7) + ((lane & 16) >> 1);
                int kc = ks * 2 + ((lane >> 3) & 1);
                unsigned int bd = sb + AOP_H + (unsigned int)(row * 512) +
                                  (unsigned int)((kc ^ (row & 7)) << 4);
                ldmatrix_x4(vh, bd);
                ldmatrix_x4(vl, bd + (AOP_L - AOP_H));
            }
            #pragma unroll
            for (int nf = 0; nf < 2; nf++) {
                int hh = nf * 2;
                mma_bf16(oacc[nf], ph, vh[hh], vh[hh+1]);
                mma_bf16(oacc[nf], pl, vh[hh], vh[hh+1]);
                mma_bf16(oacc[nf], ph, vl[hh], vl[hh+1]);
            }
        }
    }

    // epilogue -> g_CT
    {
        int row = q0 + wm * 16 + (lane >> 2);
        #pragma unroll
        for (int nf = 0; nf < 2; nf++) {
            int col = h * 64 + wn * 16 + nf * 8 + (lane & 3) * 2;
            *(float2*)(g_CT + ((size_t)(b * SS + row) * DD) + col) =
                make_float2(oacc[nf][0], oacc[nf][1]);
            *(float2*)(g_CT + ((size_t)(b * SS + row + 8) * DD) + col) =
                make_float2(oacc[nf][2], oacc[nf][3]);
        }
    }
}

// ---------------------------------------------------------------------------
extern "C" void kernel_launch(void* const* d_in, const int* in_sizes, int n_in,
                              void* d_out, int out_size)
{
    const float* q      = (const float*)d_in[0];
    const float* k      = (const float*)d_in[1];
    const float* v      = (const float*)d_in[2];
    const int*   zero_pad = (const int*)d_in[4];
    const float* qd     = (const float*)d_in[5];
    const float* Wk     = (const float*)d_in[6];
    const float* bk     = (const float*)d_in[7];
    const float* Wv     = (const float*)d_in[8];
    const float* bv     = (const float*)d_in[9];
    const float* Wo     = (const float*)d_in[10];
    const float* bo     = (const float*)d_in[11];
    const float* gammas = (const float*)d_in[12];
    float* out = (float*)d_out;

    const int GEMM_SMEM = 3 * STG_STRIDE;    // 98304 B
    cudaFuncSetAttribute(gemm_mma_kernel<1>,
                         cudaFuncAttributeMaxDynamicSharedMemorySize, GEMM_SMEM);
    cudaFuncSetAttribute(gemm_mma_kernel<0>,
                         cudaFuncAttributeMaxDynamicSharedMemorySize, GEMM_SMEM);
    cudaFuncSetAttribute(akt_attn_kernel,
                         cudaFuncAttributeMaxDynamicSharedMemorySize, ATTN_SMEM_TOT);

    const int N_IN = BB * SS * DD;
    const int N_QD = BB * SS * SS;
    const int N_W  = DD * DD;

    convert_split<<<N_IN / 2048, 256>>>(q,  0, N_IN);
    convert_split<<<N_IN / 2048, 256>>>(k,  1, N_IN);
    convert_split<<<N_IN / 2048, 256>>>(v,  2, N_IN);
    convert_split<<<N_W  / 2048, 256>>>(Wk, 3, N_W);
    convert_split<<<N_W  / 2048, 256>>>(Wv, 4, N_W);
    convert_split<<<N_W  / 2048, 256>>>(Wo, 5, N_W);
    diff_kernel<<<N_QD / 1024, 256>>>(qd);

    gemm_mma_kernel<1><<<dim3(128, 4, 3), 256, GEMM_SMEM>>>(bk, bv, nullptr);

    akt_attn_kernel<<<dim3(8, 256), 512, ATTN_SMEM_TOT>>>(gammas, zero_pad);

    convert_split<<<N_IN / 2048, 256>>>(nullptr, 6, N_IN);

    gemm_mma_kernel<0><<<dim3(128, 4, 1), 256, GEMM_SMEM>>>(bo, nullptr, out);
}

// round 15
// speedup vs baseline: 1.2864x; 1.0087x over previous
#include <cuda_runtime.h>
#include <cuda_bf16.h>
#include <stdint.h>
#include <math.h>

#define BB 32
#define SS 512
#define DD 512
#define HH 8
#define DFF 64

// Scratch (allocation-free)
__device__ float g_DF[BB*SS*SS];      // exp(sigmoid(qd)) precomputed

// bf16 hi/lo split operand buffers (GEMM inputs; g_Ah[0] reused for attn out)
__device__ __nv_bfloat16 g_Ah[3][BB*SS*DD];
__device__ __nv_bfloat16 g_Al[3][BB*SS*DD];
__device__ __nv_bfloat16 g_Wh[3][DD*DD];
__device__ __nv_bfloat16 g_Wl[3][DD*DD];

// attention operands (written by projection epilogue)
__device__ __nv_bfloat16 g_Qh[BB*HH*SS*DFF];   // [bh][s][df], pre-scaled 1/8
__device__ __nv_bfloat16 g_Ql[BB*HH*SS*DFF];
__device__ __nv_bfloat16 g_Kh[BB*HH*SS*DFF];   // [bh][s][df]
__device__ __nv_bfloat16 g_Kl[BB*HH*SS*DFF];
__device__ __nv_bfloat16 g_Vh[BB*HH*DFF*SS];   // [bh][df][s]  (transposed)
__device__ __nv_bfloat16 g_Vl[BB*HH*DFF*SS];

// ===========================================================================
// PTX helpers (portable sm_80+ subset)
// ===========================================================================
__device__ __forceinline__ unsigned int smem_to_u32(const void* p) {
    unsigned int a;
    asm("{ .reg .u64 t; cvta.to.shared.u64 t, %1; cvt.u32.u64 %0, t; }"
        : "=r"(a) : "l"(p));
    return a;
}

__device__ __forceinline__ void cp_async16(unsigned int dst, const void* src) {
    asm volatile("cp.async.cg.shared.global [%0], [%1], 16;\n"
                 :: "r"(dst), "l"(src));
}
#define CP_COMMIT() asm volatile("cp.async.commit_group;\n" ::: "memory")
#define CP_WAIT1()  asm volatile("cp.async.wait_group 1;\n" ::: "memory")
#define CP_WAIT0()  asm volatile("cp.async.wait_group 0;\n" ::: "memory")

__device__ __forceinline__ void ldmatrix_x4(unsigned int* r, unsigned int addr) {
    asm volatile("ldmatrix.sync.aligned.m8n8.x4.shared.b16 {%0,%1,%2,%3}, [%4];"
                 : "=r"(r[0]), "=r"(r[1]), "=r"(r[2]), "=r"(r[3]) : "r"(addr));
}

__device__ __forceinline__ void mma_bf16(float* c, const unsigned int* a,
                                         unsigned int b0, unsigned int b1) {
    asm volatile(
        "mma.sync.aligned.m16n8k16.row.col.f32.bf16.bf16.f32 "
        "{%0,%1,%2,%3}, {%4,%5,%6,%7}, {%8,%9}, {%0,%1,%2,%3};"
        : "+f"(c[0]), "+f"(c[1]), "+f"(c[2]), "+f"(c[3])
        : "r"(a[0]), "r"(a[1]), "r"(a[2]), "r"(a[3]), "r"(b0), "r"(b1));
}

__device__ __forceinline__ unsigned int bfpack(float x, float y) {
    __nv_bfloat16 h0 = __float2bfloat16(x), h1 = __float2bfloat16(y);
    return (unsigned int)__bfloat16_as_ushort(h0) |
           ((unsigned int)__bfloat16_as_ushort(h1) << 16);
}

// ===========================================================================
// Precompute diff = exp(sigmoid(qd))
// ===========================================================================
__global__ __launch_bounds__(256)
void diff_kernel(const float* __restrict__ qd)
{
    int idx = (blockIdx.x * 256 + threadIdx.x) << 2;
    float4 a = *(const float4*)(qd + idx);
    float4 o;
    o.x = __expf(1.f / (1.f + __expf(-a.x)));
    o.y = __expf(1.f / (1.f + __expf(-a.y)));
    o.z = __expf(1.f / (1.f + __expf(-a.z)));
    o.w = __expf(1.f / (1.f + __expf(-a.w)));
    *(float4*)(g_DF + idx) = o;
}

// ===========================================================================
// Convert fp32 -> bf16 hi/lo split.  which: 0-2 inputs, 3-5 weights
// ===========================================================================
__global__ __launch_bounds__(256)
void convert_split(const float* __restrict__ src, int which, int n)
{
    __nv_bfloat16 *hi, *lo;
    if (which < 3) { hi = g_Ah[which];   lo = g_Al[which]; }
    else           { hi = g_Wh[which-3]; lo = g_Wl[which-3]; }

    int idx = (blockIdx.x * 256 + threadIdx.x) << 3;
    if (idx >= n) return;
    float4 a = *(const float4*)(src + idx);
    float4 b = *(const float4*)(src + idx + 4);
    float v[8] = {a.x, a.y, a.z, a.w, b.x, b.y, b.z, b.w};
    unsigned int hw[4], lw[4];
    #pragma unroll
    for (int i = 0; i < 4; i++) {
        float x = v[2*i], y = v[2*i+1];
        __nv_bfloat16 h0 = __float2bfloat16(x), h1 = __float2bfloat16(y);
        float r0 = x - __bfloat162float(h0), r1 = y - __bfloat162float(h1);
        hw[i] = (unsigned int)__bfloat16_as_ushort(h0) |
                ((unsigned int)__bfloat16_as_ushort(h1) << 16);
        lw[i] = bfpack(r0, r1);
    }
    *(uint4*)(hi + idx) = make_uint4(hw[0], hw[1], hw[2], hw[3]);
    *(uint4*)(lo + idx) = make_uint4(lw[0], lw[1], lw[2], lw[3]);
}

// ===========================================================================
// mma.sync bf16 3-term split GEMM.  Tile 128x128, BK=32, 3-stage cp.async.
// MODE 0: A=g_Ah[0]/g_Al[0] (attention out), W=Wo -> Cout fp32 row-major.
// MODE 1: z=0/1 -> g_Qh/l,g_Kh/l ([bh][s][df], Q scaled 1/8);
//         z=2 -> g_Vh/l transposed [bh][df][s].
// ===========================================================================
#define STG_STRIDE 32768
#define AH_OFF 0
#define AL_OFF 8192
#define BH_OFF 16384
#define BL_OFF 24576

__device__ __forceinline__ void load_stage(
    const __nv_bfloat16* __restrict__ Ah, const __nv_bfloat16* __restrict__ Al,
    const __nv_bfloat16* __restrict__ Bh, const __nv_bfloat16* __restrict__ Bl,
    unsigned int st, int rBase, int cBase, int kt, int tid)
{
    #pragma unroll
    for (int i = 0; i < 2; i++) {
        int c   = tid * 2 + i;
        int row = c >> 2;
        int kc  = c & 3;
        unsigned int dsw = (unsigned int)(row * 64) +
                           (unsigned int)((kc ^ ((row >> 1) & 3)) << 4);
        size_t aoff = (size_t)(rBase + row) * DD + kt * 32 + kc * 8;
        size_t boff = (size_t)(cBase + row) * DD + kt * 32 + kc * 8;
        cp_async16(st + AH_OFF + dsw, Ah + aoff);
        cp_async16(st + AL_OFF + dsw, Al + aoff);
        cp_async16(st + BH_OFF + dsw, Bh + boff);
        cp_async16(st + BL_OFF + dsw, Bl + boff);
    }
}

template<int MODE>
__global__ __launch_bounds__(256)
void gemm_mma_kernel(const float* __restrict__ bias0,
                     const float* __restrict__ bias1,
                     float* __restrict__ Cout)
{
    extern __shared__ char smem[];
    const unsigned int sb = smem_to_u32(smem);
    const int tid  = threadIdx.x;
    const int lane = tid & 31;
    const int wid  = tid >> 5;
    const int warp_m = wid & 3;
    const int warp_n = wid >> 2;
    const int rBase = blockIdx.x << 7;
    const int cBase = blockIdx.y << 7;
    const int z = blockIdx.z;

    const __nv_bfloat16 *Ah, *Al, *Bh, *Bl;
    const float* bias;
    if (MODE == 0) {
        Ah = g_Ah[0]; Al = g_Al[0]; Bh = g_Wh[2]; Bl = g_Wl[2]; bias = bias0;
    } else {
        Ah = g_Ah[z]; Al = g_Al[z];
        int wi = (z == 2) ? 1 : 0;
        Bh = g_Wh[wi]; Bl = g_Wl[wi];
        bias = (z == 2) ? bias1 : bias0;
    }

    float acc[2][8][4];
    #pragma unroll
    for (int mf = 0; mf < 2; mf++)
        #pragma unroll
        for (int nf = 0; nf < 8; nf++)
            #pragma unroll
            for (int i = 0; i < 4; i++) acc[mf][nf][i] = 0.f;

    load_stage(Ah, Al, Bh, Bl, sb,              rBase, cBase, 0, tid); CP_COMMIT();
    load_stage(Ah, Al, Bh, Bl, sb + STG_STRIDE, rBase, cBase, 1, tid); CP_COMMIT();

    for (int kt = 0; kt < 16; kt++) {
        CP_WAIT1();
        __syncthreads();
        if (kt + 2 < 16)
            load_stage(Ah, Al, Bh, Bl, sb + ((kt + 2) % 3) * STG_STRIDE,
                       rBase, cBase, kt + 2, tid);
        CP_COMMIT();

        const unsigned int stB = sb + (kt % 3) * STG_STRIDE;
        #pragma unroll
        for (int ks = 0; ks < 2; ks++) {
            unsigned int ah[2][4], al[2][4], bh[4][4], bl[4][4];
            #pragma unroll
            for (int mf = 0; mf < 2; mf++) {
                int row = warp_m * 32 + mf * 16 + (lane & 15);
                int kchunk = ks * 2 + (lane >> 4);
                unsigned int ad = stB + (unsigned int)(row * 64) +
                    (unsigned int)((kchunk ^ ((row >> 1) & 3)) << 4);
                ldmatrix_x4(ah[mf], ad + AH_OFF);
                ldmatrix_x4(al[mf], ad + AL_OFF);
            }
            #pragma unroll
            for (int p = 0; p < 4; p++) {
                int row = warp_n * 64 + p * 16 + (lane & 7) + ((lane & 16) >> 1);
                int kchunk = ks * 2 + ((lane >> 3) & 1);
                unsigned int bd = stB + (unsigned int)(row * 64) +
                    (unsigned int)((kchunk ^ ((row >> 1) & 3)) << 4);
                ldmatrix_x4(bh[p], bd + BH_OFF);
                ldmatrix_x4(bl[p], bd + BL_OFF);
            }
            #pragma unroll
            for (int mf = 0; mf < 2; mf++)
                #pragma unroll
                for (int nf = 0; nf < 8; nf++) {
                    int p = nf >> 1, hh = (nf & 1) * 2;
                    mma_bf16(acc[mf][nf], ah[mf], bh[p][hh], bh[p][hh+1]);
                    mma_bf16(acc[mf][nf], ah[mf], bl[p][hh], bl[p][hh+1]);
                    mma_bf16(acc[mf][nf], al[mf], bh[p][hh], bh[p][hh+1]);
                }
        }
    }

    if (MODE == 0) {
        #pragma unroll
        for (int mf = 0; mf < 2; mf++)
            #pragma unroll
            for (int nf = 0; nf < 8; nf++) {
                int col = cBase + warp_n * 64 + nf * 8 + (lane & 3) * 2;
                int row = rBase + warp_m * 32 + mf * 16 + (lane >> 2);
                float b0 = bias[col], b1 = bias[col + 1];
                float2 v0 = make_float2(acc[mf][nf][0] + b0, acc[mf][nf][1] + b1);
                float2 v1 = make_float2(acc[mf][nf][2] + b0, acc[mf][nf][3] + b1);
                *(float2*)(Cout + (size_t)row * DD + col) = v0;
                *(float2*)(Cout + (size_t)(row + 8) * DD + col) = v1;
            }
    } else if (z <= 1) {
        const float scl = (z == 0) ? 0.125f : 1.f;
        __nv_bfloat16* dh = (z == 0) ? g_Qh : g_Kh;
        __nv_bfloat16* dl = (z == 0) ? g_Ql : g_Kl;
        #pragma unroll
        for (int mf = 0; mf < 2; mf++)
            #pragma unroll
            for (int nf = 0; nf < 8; nf++) {
                int col = cBase + warp_n * 64 + nf * 8 + (lane & 3) * 2;
                int row = rBase + warp_m * 32 + mf * 16 + (lane >> 2);
                float b0 = bias[col], b1 = bias[col + 1];
                float x0 = (acc[mf][nf][0] + b0) * scl, y0 = (acc[mf][nf][1] + b1) * scl;
                float x1 = (acc[mf][nf][2] + b0) * scl, y1 = (acc[mf][nf][3] + b1) * scl;
                int h = col >> 6, df = col & 63;
                int b_ = row >> 9, s_ = row & (SS - 1);
                int bh_ = b_ * HH + h;
                size_t i0 = ((size_t)bh_ * SS + s_) * DFF + df;
                size_t i1 = ((size_t)bh_ * SS + s_ + 8) * DFF + df;
                __nv_bfloat16 h00 = __float2bfloat16(x0), h01 = __float2bfloat16(y0);
                __nv_bfloat16 h10 = __float2bfloat16(x1), h11 = __float2bfloat16(y1);
                *(unsigned int*)(dh + i0) =
                    (unsigned int)__bfloat16_as_ushort(h00) |
                    ((unsigned int)__bfloat16_as_ushort(h01) << 16);
                *(unsigned int*)(dh + i1) =
                    (unsigned int)__bfloat16_as_ushort(h10) |
                    ((unsigned int)__bfloat16_as_ushort(h11) << 16);
                *(unsigned int*)(dl + i0) =
                    bfpack(x0 - __bfloat162float(h00), y0 - __bfloat162float(h01));
                *(unsigned int*)(dl + i1) =
                    bfpack(x1 - __bfloat162float(h10), y1 - __bfloat162float(h11));
            }
    } else {
        float* SV = (float*)smem;       // 128 cols x 132 rows
        __syncthreads();
        #pragma unroll
        for (int mf = 0; mf < 2; mf++)
            #pragma unroll
            for (int nf = 0; nf < 8; nf++) {
                int cl = warp_n * 64 + nf * 8 + (lane & 3) * 2;
                int rl = warp_m * 32 + mf * 16 + (lane >> 2);
                float b0 = bias[cBase + cl], b1 = bias[cBase + cl + 1];
                SV[cl * 132 + rl]       = acc[mf][nf][0] + b0;
                SV[(cl+1) * 132 + rl]   = acc[mf][nf][1] + b1;
                SV[cl * 132 + rl + 8]   = acc[mf][nf][2] + b0;
                SV[(cl+1) * 132 + rl+8] = acc[mf][nf][3] + b1;
            }
        __syncthreads();
        int ldf = tid >> 1;
        int s0  = (tid & 1) * 64;
        int gcol = cBase + ldf;
        int h = gcol >> 6, df = gcol & 63;
        int b_ = rBase >> 9, sBase = rBase & (SS - 1);
        size_t base = (((size_t)(b_ * HH + h) * DFF + df) * SS) + sBase + s0;
        #pragma unroll
        for (int u = 0; u < 64; u += 8) {
            float4 x = *(float4*)&SV[ldf * 132 + s0 + u];
            float4 y = *(float4*)&SV[ldf * 132 + s0 + u + 4];
            float vv[8] = {x.x, x.y, x.z, x.w, y.x, y.y, y.z, y.w};
            unsigned int hw[4], lw[4];
            #pragma unroll
            for (int i = 0; i < 4; i++) {
                __nv_bfloat16 p0 = __float2bfloat16(vv[2*i]);
                __nv_bfloat16 p1 = __float2bfloat16(vv[2*i+1]);
                hw[i] = (unsigned int)__bfloat16_as_ushort(p0) |
                        ((unsigned int)__bfloat16_as_ushort(p1) << 16);
                lw[i] = bfpack(vv[2*i] - __bfloat162float(p0),
                               vv[2*i+1] - __bfloat162float(p1));
            }
            *(uint4*)(g_Vh + base + u) = make_uint4(hw[0], hw[1], hw[2], hw[3]);
            *(uint4*)(g_Vl + base + u) = make_uint4(lw[0], lw[1], lw[2], lw[3]);
        }
    }
}

// ===========================================================================
// Attention: 64 q-rows per CTA, 512 threads (16 warps, 4m x 4n).
// Causal-pruned mma phases; output written bf16-split to g_Ah[0]/g_Al[0].
// ===========================================================================
#define AQ_H 0
#define AQ_L 8192
#define ASC  16384
#define SCR  2176              // row stride bytes (17*128)
#define AOP_H 155648
#define AOP_L 188416
#define ATTN_SMEM_TOT 221184

__global__ __launch_bounds__(512)
void akt_attn_kernel(const float* __restrict__ gammas,
                     const int* __restrict__ zero_pad)
{
    extern __shared__ char smem[];
    const unsigned int sb = smem_to_u32(smem);
    const int tid = threadIdx.x, lane = tid & 31, wid = tid >> 5;
    const int bh = blockIdx.y, b = bh >> 3, h = bh & 7;
    const int q0 = blockIdx.x << 6, qmax = q0 + 63;
    const int njt = (qmax >> 8) + 1;              // 256-wide j-tiles
    const int ksmax16 = ((qmax >> 4) + 1) << 4;   // live k bound (16-aligned)
    const int wm = wid & 3, wn = wid >> 2;        // 4m x 4n

    const __nv_bfloat16* Qh = g_Qh + ((size_t)bh * SS + q0) * DFF;
    const __nv_bfloat16* Ql = g_Ql + ((size_t)bh * SS + q0) * DFF;
    const __nv_bfloat16* Kh = g_Kh + (size_t)bh * SS * DFF;
    const __nv_bfloat16* Kl = g_Kl + (size_t)bh * SS * DFF;
    const __nv_bfloat16* Vh = g_Vh + (size_t)bh * DFF * SS;
    const __nv_bfloat16* Vl = g_Vl + (size_t)bh * DFF * SS;

    // ---- load Q (64x128B hi/lo) ----
    {
        int row = tid >> 3, kc = tid & 7;
        unsigned int dsw = (unsigned int)(row * 128) +
                           (unsigned int)((kc ^ (row & 7)) << 4);
        cp_async16(sb + AQ_H + dsw, Qh + row * DFF + kc * 8);
        cp_async16(sb + AQ_L + dsw, Ql + row * DFF + kc * 8);
    }
    // ---- K tile 0 (rows <= qmax only) ----
    #pragma unroll
    for (int u = 0; u < 4; u++) {
        int c = u * 512 + tid;
        int row = c >> 3, kc = c & 7;
        if (row <= qmax) {
            unsigned int dsw = (unsigned int)(row * 128) +
                               (unsigned int)((kc ^ (row & 7)) << 4);
            cp_async16(sb + AOP_H + dsw, Kh + row * DFF + kc * 8);
            cp_async16(sb + AOP_L + dsw, Kl + row * DFF + kc * 8);
        }
    }
    CP_COMMIT();
    CP_WAIT0();
    __syncthreads();

    // ---- Phase 1: scores via mma (causal-pruned n-blocks) ----
    for (int jt = 0; jt < njt; jt++) {
        if (jt > 0) {
            __syncthreads();
            #pragma unroll
            for (int u = 0; u < 4; u++) {
                int c = u * 512 + tid;
                int row = c >> 3, kc = c & 7;
                if (jt * 256 + row <= qmax) {
                    unsigned int dsw = (unsigned int)(row * 128) +
                                       (unsigned int)((kc ^ (row & 7)) << 4);
                    cp_async16(sb + AOP_H + dsw, Kh + (jt*256 + row) * DFF + kc * 8);
                    cp_async16(sb + AOP_L + dsw, Kl + (jt*256 + row) * DFF + kc * 8);
                }
            }
            CP_COMMIT();
            CP_WAIT0();
            __syncthreads();
        }
        if (jt * 256 + wn * 64 <= qmax) {   // warp-uniform liveness
            float acc[8][4];
            #pragma unroll
            for (int nf = 0; nf < 8; nf++)
                #pragma unroll
                for (int i = 0; i < 4; i++) acc[nf][i] = 0.f;

            #pragma unroll
            for (int ks = 0; ks < 4; ks++) {
                unsigned int ah[4], al[4], bhf[4][4], blf[4][4];
                {
                    int row = wm * 16 + (lane & 15);
                    int kc = ks * 2 + (lane >> 4);
                    unsigned int ad = sb + (unsigned int)(row * 128) +
                                      (unsigned int)((kc ^ (row & 7)) << 4);
                    ldmatrix_x4(ah, ad + AQ_H);
                    ldmatrix_x4(al, ad + AQ_L);
                }
                #pragma unroll
                for (int p = 0; p < 4; p++) {
                    int row = wn * 64 + p * 16 + (lane & 7) + ((lane & 16) >> 1);
                    int kc = ks * 2 + ((lane >> 3) & 1);
                    unsigned int bd = sb + AOP_H + (unsigned int)(row * 128) +
                                      (unsigned int)((kc ^ (row & 7)) << 4);
                    ldmatrix_x4(bhf[p], bd);
                    ldmatrix_x4(blf[p], bd + (AOP_L - AOP_H));
                }
                #pragma unroll
                for (int nf = 0; nf < 8; nf++) {
                    int p = nf >> 1, hh = (nf & 1) * 2;
                    mma_bf16(acc[nf], ah, bhf[p][hh], bhf[p][hh+1]);
                    mma_bf16(acc[nf], ah, blf[p][hh], blf[p][hh+1]);
                    mma_bf16(acc[nf], al, bhf[p][hh], bhf[p][hh+1]);
                }
            }
            int r0 = wm * 16 + (lane >> 2);
            #pragma unroll
            for (int nf = 0; nf < 8; nf++) {
                int col = jt * 256 + wn * 64 + nf * 8 + (lane & 3) * 2;
                unsigned int o0 = (unsigned int)(r0 * SCR) +
                    (unsigned int)((((col >> 2) ^ (r0 & 7)) << 4) + (col & 3) * 4);
                unsigned int o1 = o0 + 8 * SCR;
                *(float2*)(smem + ASC + o0) = make_float2(acc[nf][0], acc[nf][1]);
                *(float2*)(smem + ASC + o1) = make_float2(acc[nf][2], acc[nf][3]);
            }
        }
    }
    __syncthreads();

    // ---- kick V tile 0 load (live columns only) ----
    #pragma unroll
    for (int u = 0; u < 4; u++) {
        int c = u * 512 + tid;
        int row = c >> 5, kc = c & 31;
        if (kc * 8 < ksmax16) {
            unsigned int dsw = (unsigned int)(row * 512) +
                               (unsigned int)((kc ^ (row & 7)) << 4);
            cp_async16(sb + AOP_H + dsw, Vh + row * SS + kc * 8);
            cp_async16(sb + AOP_L + dsw, Vl + row * SS + kc * 8);
        }
    }
    CP_COMMIT();

    // ---- Phase 2 ----
    const float gamma = -log1pf(__expf(gammas[h]));
    const int zp = *zero_pad;
    const int nch3 = (ksmax16 + 31) >> 5;     // P zero-fill coverage

    for (int pass = 0; pass < 4; pass++) {
        const int qr = (pass << 4) + wid;
        const int qg = q0 + qr;
        const int qtop = qg >> 5;
        const unsigned int rbase = (unsigned int)(qr * SCR);
        float sv[16], pv[16], tot[16];

        #pragma unroll
        for (int i = 0; i < 16; i++) {
            if (i <= qtop) {
                int j = (i << 5) + lane;
                unsigned int off = ((((j >> 2) ^ (qr & 7)) << 4) + (j & 3) * 4);
                sv[i] = *(float*)(smem + ASC + rbase + off);
            }
        }

        float m = -3.0e38f;
        #pragma unroll
        for (int i = 0; i < 16; i++) {
            if (i <= qtop) {
                int j = (i << 5) + lane;
                if (j <= qg) m = fmaxf(m, sv[i]);
            }
        }
        #pragma unroll
        for (int off = 16; off > 0; off >>= 1)
            m = fmaxf(m, __shfl_xor_sync(0xffffffffu, m, off));
        float ssum = 0.f;
        #pragma unroll
        for (int i = 0; i < 16; i++) {
            if (i <= qtop) {
                int j = (i << 5) + lane;
                pv[i] = (j <= qg) ? __expf(sv[i] - m) : 0.f;
                ssum += pv[i];
            }
        }
        #pragma unroll
        for (int off = 16; off > 0; off >>= 1)
            ssum += __shfl_xor_sync(0xffffffffu, ssum, off);
        const float inv1 = 1.f / ssum;

        #pragma unroll
        for (int i = 0; i < 16; i++) {
            if (i <= qtop) {
                float s = pv[i] * inv1;
                #pragma unroll
                for (int off = 1; off < 32; off <<= 1) {
                    float t = __shfl_up_sync(0xffffffffu, s, off);
                    if (lane >= off) s += t;
                }
                pv[i] = s;
                tot[i] = __shfl_sync(0xffffffffu, s, 31);
            }
        }
        const float* dfrow = g_DF + ((size_t)b * SS + qg) * SS;
        float pre = 0.f;
        #pragma unroll
        for (int i = 0; i < 16; i++) {
            if (i <= qtop) {
                int j = (i << 5) + lane;
                float c = pre + pv[i];
                pre += tot[i];
                float rem = fmaxf(1.f - c, 0.f);
                float dsc = (j <= qg) ? sqrtf(rem * (float)(qg - j)) : 0.f;
                float te = __expf(dsc * gamma * dfrow[j]);
                te = fminf(fmaxf(te, 1e-5f), 1e5f);
                pv[i] = (j <= qg) ? sv[i] * te : -3.0e38f;
            }
        }

        float m2 = -3.0e38f;
        #pragma unroll
        for (int i = 0; i < 16; i++)
            if (i <= qtop) m2 = fmaxf(m2, pv[i]);
        #pragma unroll
        for (int off = 16; off > 0; off >>= 1)
            m2 = fmaxf(m2, __shfl_xor_sync(0xffffffffu, m2, off));
        float sum2 = 0.f;
        #pragma unroll
        for (int i = 0; i < 16; i++) {
            if (i <= qtop) {
                int j = (i << 5) + lane;
                float e = (j <= qg) ? __expf(pv[i] - m2) : 0.f;
                sv[i] = e;
                sum2 += e;
            }
        }
        #pragma unroll
        for (int off = 16; off > 0; off >>= 1)
            sum2 += __shfl_xor_sync(0xffffffffu, sum2, off);
        const float inv2 = 1.f / sum2;
        const bool zrow = (zp != 0) && (qg == 0);

        // write P (bf16 hi/lo) aliased onto this row's SC bytes
        #pragma unroll
        for (int i = 0; i < 16; i++) {
            if (i < nch3) {
                int j = (i << 5) + lane;
                float pr = (i <= qtop && !zrow) ? sv[i] * inv2 : 0.f;
                __nv_bfloat16 ph = __float2bfloat16(pr);
                __nv_bfloat16 pl = __float2bfloat16(pr - __bfloat162float(ph));
                unsigned int off2 = (unsigned int)((((j >> 3) ^ (qr & 7)) << 4) +
                                                   ((j & 7) << 1));
                *(__nv_bfloat16*)(smem + ASC + rbase + off2) = ph;
                *(__nv_bfloat16*)(smem + ASC + rbase + 1024 + off2) = pl;
            }
        }
    }

    CP_WAIT0();
    __syncthreads();   // all P written, V tile 0 ready

    // ---- Phase 3: out = P @ V via mma (causal-pruned ks) ----
    float oacc[2][4];
    #pragma unroll
    for (int nf = 0; nf < 2; nf++)
        #pragma unroll
        for (int i = 0; i < 4; i++) oacc[nf][i] = 0.f;

    for (int jt = 0; jt < njt; jt++) {
        if (jt > 0) {
            __syncthreads();
            #pragma unroll
            for (int u = 0; u < 4; u++) {
                int c = u * 512 + tid;
                int row = c >> 5, kc = c & 31;
                if (jt * 256 + kc * 8 < ksmax16) {
                    unsigned int dsw = (unsigned int)(row * 512) +
                                       (unsigned int)((kc ^ (row & 7)) << 4);
                    cp_async16(sb + AOP_H + dsw, Vh + row * SS + jt*256 + kc * 8);
                    cp_async16(sb + AOP_L + dsw, Vl + row * SS + jt*256 + kc * 8);
                }
            }
            CP_COMMIT();
            CP_WAIT0();
            __syncthreads();
        }
        const int kslim = min(16, (ksmax16 >> 4) - jt * 16);
        for (int ks = 0; ks < kslim; ks++) {
            unsigned int ph[4], pl[4], vh[4], vl[4];
            {
                int row = wm * 16 + (lane & 15);
                int kc = jt * 32 + ks * 2 + (lane >> 4);
                unsigned int ad = sb + ASC + (unsigned int)(row * SCR) +
                                  (unsigned int)((kc ^ (row & 7)) << 4);
                ldmatrix_x4(ph, ad);
                ldmatrix_x4(pl, ad + 1024);
            }
            {
                int row = wn * 16 + (lane & 7) + ((lane & 16) >> 1);
                int kc = ks * 2 + ((lane >> 3) & 1);
                unsigned int bd = sb + AOP_H + (unsigned int)(row * 512) +
                                  (unsigned int)((kc ^ (row & 7)) << 4);
                ldmatrix_x4(vh, bd);
                ldmatrix_x4(vl, bd + (AOP_L - AOP_H));
            }
            #pragma unroll
            for (int nf = 0; nf < 2; nf++) {
                int hh = nf * 2;
                mma_bf16(oacc[nf], ph, vh[hh], vh[hh+1]);
                mma_bf16(oacc[nf], pl, vh[hh], vh[hh+1]);
                mma_bf16(oacc[nf], ph, vl[hh], vl[hh+1]);
            }
        }
    }

    // epilogue: bf16 hi/lo split straight into g_Ah[0]/g_Al[0]  [B,S,D]
    {
        int row = q0 + wm * 16 + (lane >> 2);
        #pragma unroll
        for (int nf = 0; nf < 2; nf++) {
            int col = h * 64 + wn * 16 + nf * 8 + (lane & 3) * 2;
            size_t i0 = ((size_t)(b * SS + row)     * DD) + col;
            size_t i1 = ((size_t)(b * SS + row + 8) * DD) + col;
            float x0 = oacc[nf][0], y0 = oacc[nf][1];
            float x1 = oacc[nf][2], y1 = oacc[nf][3];
            __nv_bfloat16 h00 = __float2bfloat16(x0), h01 = __float2bfloat16(y0);
            __nv_bfloat16 h10 = __float2bfloat16(x1), h11 = __float2bfloat16(y1);
            *(unsigned int*)(g_Ah[0] + i0) =
                (unsigned int)__bfloat16_as_ushort(h00) |
                ((unsigned int)__bfloat16_as_ushort(h01) << 16);
            *(unsigned int*)(g_Ah[0] + i1) =
                (unsigned int)__bfloat16_as_ushort(h10) |
                ((unsigned int)__bfloat16_as_ushort(h11) << 16);
            *(unsigned int*)(g_Al[0] + i0) =
                bfpack(x0 - __bfloat162float(h00), y0 - __bfloat162float(h01));
            *(unsigned int*)(g_Al[0] + i1) =
                bfpack(x1 - __bfloat162float(h10), y1 - __bfloat162float(h11));
        }
    }
}

// ---------------------------------------------------------------------------
extern "C" void kernel_launch(void* const* d_in, const int* in_sizes, int n_in,
                              void* d_out, int out_size)
{
    const float* q      = (const float*)d_in[0];
    const float* k      = (const float*)d_in[1];
    const float* v      = (const float*)d_in[2];
    const int*   zero_pad = (const int*)d_in[4];
    const float* qd     = (const float*)d_in[5];
    const float* Wk     = (const float*)d_in[6];
    const float* bk     = (const float*)d_in[7];
    const float* Wv     = (const float*)d_in[8];
    const float* bv     = (const float*)d_in[9];
    const float* Wo     = (const float*)d_in[10];
    const float* bo     = (const float*)d_in[11];
    const float* gammas = (const float*)d_in[12];
    float* out = (float*)d_out;

    const int GEMM_SMEM = 3 * STG_STRIDE;    // 98304 B
    cudaFuncSetAttribute(gemm_mma_kernel<1>,
                         cudaFuncAttributeMaxDynamicSharedMemorySize, GEMM_SMEM);
    cudaFuncSetAttribute(gemm_mma_kernel<0>,
                         cudaFuncAttributeMaxDynamicSharedMemorySize, GEMM_SMEM);
    cudaFuncSetAttribute(akt_attn_kernel,
                         cudaFuncAttributeMaxDynamicSharedMemorySize, ATTN_SMEM_TOT);

    const int N_IN = BB * SS * DD;
    const int N_QD = BB * SS * SS;
    const int N_W  = DD * DD;

    convert_split<<<N_IN / 2048, 256>>>(q,  0, N_IN);
    convert_split<<<N_IN / 2048, 256>>>(k,  1, N_IN);
    convert_split<<<N_IN / 2048, 256>>>(v,  2, N_IN);
    convert_split<<<N_W  / 2048, 256>>>(Wk, 3, N_W);
    convert_split<<<N_W  / 2048, 256>>>(Wv, 4, N_W);
    convert_split<<<N_W  / 2048, 256>>>(Wo, 5, N_W);
    diff_kernel<<<N_QD / 1024, 256>>>(qd);

    gemm_mma_kernel<1><<<dim3(128, 4, 3), 256, GEMM_SMEM>>>(bk, bv, nullptr);

    akt_attn_kernel<<<dim3(8, 256), 512, ATTN_SMEM_TOT>>>(gammas, zero_pad);

    gemm_mma_kernel<0><<<dim3(128, 4, 1), 256, GEMM_SMEM>>>(bo, nullptr, out);
}

// round 17
// speedup vs baseline: 1.2921x; 1.0044x over previous
#include <cuda_runtime.h>
#include <cuda_bf16.h>
#include <stdint.h>
#include <math.h>

#define BB 32
#define SS 512
#define DD 512
#define HH 8
#define DFF 64

// Scratch (allocation-free)
__device__ float g_DF[BB*SS*SS];      // exp(sigmoid(qd)) precomputed

// bf16 hi/lo split operand buffers (GEMM inputs; g_Ah[0] reused for attn out)
__device__ __nv_bfloat16 g_Ah[3][BB*SS*DD];
__device__ __nv_bfloat16 g_Al[3][BB*SS*DD];
__device__ __nv_bfloat16 g_Wh[3][DD*DD];
__device__ __nv_bfloat16 g_Wl[3][DD*DD];

// attention operands (written by projection epilogue)
__device__ __nv_bfloat16 g_Qh[BB*HH*SS*DFF];   // [bh][s][df], pre-scaled 1/8
__device__ __nv_bfloat16 g_Ql[BB*HH*SS*DFF];
__device__ __nv_bfloat16 g_Kh[BB*HH*SS*DFF];   // [bh][s][df]
__device__ __nv_bfloat16 g_Kl[BB*HH*SS*DFF];
__device__ __nv_bfloat16 g_Vh[BB*HH*DFF*SS];   // [bh][df][s]  (transposed)
__device__ __nv_bfloat16 g_Vl[BB*HH*DFF*SS];

// ===========================================================================
// PTX helpers (portable sm_80+ subset)
// ===========================================================================
__device__ __forceinline__ unsigned int smem_to_u32(const void* p) {
    unsigned int a;
    asm("{ .reg .u64 t; cvta.to.shared.u64 t, %1; cvt.u32.u64 %0, t; }"
        : "=r"(a) : "l"(p));
    return a;
}

__device__ __forceinline__ void cp_async16(unsigned int dst, const void* src) {
    asm volatile("cp.async.cg.shared.global [%0], [%1], 16;\n"
                 :: "r"(dst), "l"(src));
}
#define CP_COMMIT() asm volatile("cp.async.commit_group;\n" ::: "memory")
#define CP_WAIT1()  asm volatile("cp.async.wait_group 1;\n" ::: "memory")
#define CP_WAIT0()  asm volatile("cp.async.wait_group 0;\n" ::: "memory")

__device__ __forceinline__ void ldmatrix_x4(unsigned int* r, unsigned int addr) {
    asm volatile("ldmatrix.sync.aligned.m8n8.x4.shared.b16 {%0,%1,%2,%3}, [%4];"
                 : "=r"(r[0]), "=r"(r[1]), "=r"(r[2]), "=r"(r[3]) : "r"(addr));
}

__device__ __forceinline__ void mma_bf16(float* c, const unsigned int* a,
                                         unsigned int b0, unsigned int b1) {
    asm volatile(
        "mma.sync.aligned.m16n8k16.row.col.f32.bf16.bf16.f32 "
        "{%0,%1,%2,%3}, {%4,%5,%6,%7}, {%8,%9}, {%0,%1,%2,%3};"
        : "+f"(c[0]), "+f"(c[1]), "+f"(c[2]), "+f"(c[3])
        : "r"(a[0]), "r"(a[1]), "r"(a[2]), "r"(a[3]), "r"(b0), "r"(b1));
}

__device__ __forceinline__ unsigned int bfpack(float x, float y) {
    __nv_bfloat16 h0 = __float2bfloat16(x), h1 = __float2bfloat16(y);
    return (unsigned int)__bfloat16_as_ushort(h0) |
           ((unsigned int)__bfloat16_as_ushort(h1) << 16);
}

// ===========================================================================
// Precompute diff = exp(sigmoid(qd))
// ===========================================================================
__global__ __launch_bounds__(256)
void diff_kernel(const float* __restrict__ qd)
{
    int idx = (blockIdx.x * 256 + threadIdx.x) << 2;
    float4 a = *(const float4*)(qd + idx);
    float4 o;
    o.x = __expf(1.f / (1.f + __expf(-a.x)));
    o.y = __expf(1.f / (1.f + __expf(-a.y)));
    o.z = __expf(1.f / (1.f + __expf(-a.z)));
    o.w = __expf(1.f / (1.f + __expf(-a.w)));
    *(float4*)(g_DF + idx) = o;
}

// ===========================================================================
// Convert fp32 -> bf16 hi/lo split.  which: 0-2 inputs, 3-5 weights
// ===========================================================================
__global__ __launch_bounds__(256)
void convert_split(const float* __restrict__ src, int which, int n)
{
    __nv_bfloat16 *hi, *lo;
    if (which < 3) { hi = g_Ah[which];   lo = g_Al[which]; }
    else           { hi = g_Wh[which-3]; lo = g_Wl[which-3]; }

    int idx = (blockIdx.x * 256 + threadIdx.x) << 3;
    if (idx >= n) return;
    float4 a = *(const float4*)(src + idx);
    float4 b = *(const float4*)(src + idx + 4);
    float v[8] = {a.x, a.y, a.z, a.w, b.x, b.y, b.z, b.w};
    unsigned int hw[4], lw[4];
    #pragma unroll
    for (int i = 0; i < 4; i++) {
        float x = v[2*i], y = v[2*i+1];
        __nv_bfloat16 h0 = __float2bfloat16(x), h1 = __float2bfloat16(y);
        float r0 = x - __bfloat162float(h0), r1 = y - __bfloat162float(h1);
        hw[i] = (unsigned int)__bfloat16_as_ushort(h0) |
                ((unsigned int)__bfloat16_as_ushort(h1) << 16);
        lw[i] = bfpack(r0, r1);
    }
    *(uint4*)(hi + idx) = make_uint4(hw[0], hw[1], hw[2], hw[3]);
    *(uint4*)(lo + idx) = make_uint4(lw[0], lw[1], lw[2], lw[3]);
}

// ===========================================================================
// mma.sync bf16 3-term split GEMM.  Tile 128x128, BK=32, 3-stage cp.async.
// MODE 0: A=g_Ah[0]/g_Al[0] (attention out), W=Wo -> Cout fp32 row-major.
// MODE 1: z=0/1 -> g_Qh/l,g_Kh/l ([bh][s][df], Q scaled 1/8);
//         z=2 -> g_Vh/l transposed [bh][df][s].
// ===========================================================================
#define STG_STRIDE 32768
#define AH_OFF 0
#define AL_OFF 8192
#define BH_OFF 16384
#define BL_OFF 24576

__device__ __forceinline__ void load_stage(
    const __nv_bfloat16* __restrict__ Ah, const __nv_bfloat16* __restrict__ Al,
    const __nv_bfloat16* __restrict__ Bh, const __nv_bfloat16* __restrict__ Bl,
    unsigned int st, int rBase, int cBase, int kt, int tid)
{
    #pragma unroll
    for (int i = 0; i < 2; i++) {
        int c   = tid * 2 + i;
        int row = c >> 2;
        int kc  = c & 3;
        unsigned int dsw = (unsigned int)(row * 64) +
                           (unsigned int)((kc ^ ((row >> 1) & 3)) << 4);
        size_t aoff = (size_t)(rBase + row) * DD + kt * 32 + kc * 8;
        size_t boff = (size_t)(cBase + row) * DD + kt * 32 + kc * 8;
        cp_async16(st + AH_OFF + dsw, Ah + aoff);
        cp_async16(st + AL_OFF + dsw, Al + aoff);
        cp_async16(st + BH_OFF + dsw, Bh + boff);
        cp_async16(st + BL_OFF + dsw, Bl + boff);
    }
}

template<int MODE>
__global__ __launch_bounds__(256)
void gemm_mma_kernel(const float* __restrict__ bias0,
                     const float* __restrict__ bias1,
                     float* __restrict__ Cout)
{
    extern __shared__ char smem[];
    const unsigned int sb = smem_to_u32(smem);
    const int tid  = threadIdx.x;
    const int lane = tid & 31;
    const int wid  = tid >> 5;
    const int warp_m = wid & 3;
    const int warp_n = wid >> 2;
    const int rBase = blockIdx.x << 7;
    const int cBase = blockIdx.y << 7;
    const int z = blockIdx.z;

    const __nv_bfloat16 *Ah, *Al, *Bh, *Bl;
    const float* bias;
    if (MODE == 0) {
        Ah = g_Ah[0]; Al = g_Al[0]; Bh = g_Wh[2]; Bl = g_Wl[2]; bias = bias0;
    } else {
        Ah = g_Ah[z]; Al = g_Al[z];
        int wi = (z == 2) ? 1 : 0;
        Bh = g_Wh[wi]; Bl = g_Wl[wi];
        bias = (z == 2) ? bias1 : bias0;
    }

    float acc[2][8][4];
    #pragma unroll
    for (int mf = 0; mf < 2; mf++)
        #pragma unroll
        for (int nf = 0; nf < 8; nf++)
            #pragma unroll
            for (int i = 0; i < 4; i++) acc[mf][nf][i] = 0.f;

    load_stage(Ah, Al, Bh, Bl, sb,              rBase, cBase, 0, tid); CP_COMMIT();
    load_stage(Ah, Al, Bh, Bl, sb + STG_STRIDE, rBase, cBase, 1, tid); CP_COMMIT();

    for (int kt = 0; kt < 16; kt++) {
        CP_WAIT1();
        __syncthreads();
        if (kt + 2 < 16)
            load_stage(Ah, Al, Bh, Bl, sb + ((kt + 2) % 3) * STG_STRIDE,
                       rBase, cBase, kt + 2, tid);
        CP_COMMIT();

        const unsigned int stB = sb + (kt % 3) * STG_STRIDE;
        #pragma unroll
        for (int ks = 0; ks < 2; ks++) {
            unsigned int ah[2][4], al[2][4], bh[4][4], bl[4][4];
            #pragma unroll
            for (int mf = 0; mf < 2; mf++) {
                int row = warp_m * 32 + mf * 16 + (lane & 15);
                int kchunk = ks * 2 + (lane >> 4);
                unsigned int ad = stB + (unsigned int)(row * 64) +
                    (unsigned int)((kchunk ^ ((row >> 1) & 3)) << 4);
                ldmatrix_x4(ah[mf], ad + AH_OFF);
                ldmatrix_x4(al[mf], ad + AL_OFF);
            }
            #pragma unroll
            for (int p = 0; p < 4; p++) {
                int row = warp_n * 64 + p * 16 + (lane & 7) + ((lane & 16) >> 1);
                int kchunk = ks * 2 + ((lane >> 3) & 1);
                unsigned int bd = stB + (unsigned int)(row * 64) +
                    (unsigned int)((kchunk ^ ((row >> 1) & 3)) << 4);
                ldmatrix_x4(bh[p], bd + BH_OFF);
                ldmatrix_x4(bl[p], bd + BL_OFF);
            }
            #pragma unroll
            for (int mf = 0; mf < 2; mf++)
                #pragma unroll
                for (int nf = 0; nf < 8; nf++) {
                    int p = nf >> 1, hh = (nf & 1) * 2;
                    mma_bf16(acc[mf][nf], ah[mf], bh[p][hh], bh[p][hh+1]);
                    mma_bf16(acc[mf][nf], ah[mf], bl[p][hh], bl[p][hh+1]);
                    mma_bf16(acc[mf][nf], al[mf], bh[p][hh], bh[p][hh+1]);
                }
        }
    }

    if (MODE == 0) {
        #pragma unroll
        for (int mf = 0; mf < 2; mf++)
            #pragma unroll
            for (int nf = 0; nf < 8; nf++) {
                int col = cBase + warp_n * 64 + nf * 8 + (lane & 3) * 2;
                int row = rBase + warp_m * 32 + mf * 16 + (lane >> 2);
                float b0 = bias[col], b1 = bias[col + 1];
                float2 v0 = make_float2(acc[mf][nf][0] + b0, acc[mf][nf][1] + b1);
                float2 v1 = make_float2(acc[mf][nf][2] + b0, acc[mf][nf][3] + b1);
                *(float2*)(Cout + (size_t)row * DD + col) = v0;
                *(float2*)(Cout + (size_t)(row + 8) * DD + col) = v1;
            }
    } else if (z <= 1) {
        const float scl = (z == 0) ? 0.125f : 1.f;
        __nv_bfloat16* dh = (z == 0) ? g_Qh : g_Kh;
        __nv_bfloat16* dl = (z == 0) ? g_Ql : g_Kl;
        #pragma unroll
        for (int mf = 0; mf < 2; mf++)
            #pragma unroll
            for (int nf = 0; nf < 8; nf++) {
                int col = cBase + warp_n * 64 + nf * 8 + (lane & 3) * 2;
                int row = rBase + warp_m * 32 + mf * 16 + (lane >> 2);
                float b0 = bias[col], b1 = bias[col + 1];
                float x0 = (acc[mf][nf][0] + b0) * scl, y0 = (acc[mf][nf][1] + b1) * scl;
                float x1 = (acc[mf][nf][2] + b0) * scl, y1 = (acc[mf][nf][3] + b1) * scl;
                int h = col >> 6, df = col & 63;
                int b_ = row >> 9, s_ = row & (SS - 1);
                int bh_ = b_ * HH + h;
                size_t i0 = ((size_t)bh_ * SS + s_) * DFF + df;
                size_t i1 = ((size_t)bh_ * SS + s_ + 8) * DFF + df;
                __nv_bfloat16 h00 = __float2bfloat16(x0), h01 = __float2bfloat16(y0);
                __nv_bfloat16 h10 = __float2bfloat16(x1), h11 = __float2bfloat16(y1);
                *(unsigned int*)(dh + i0) =
                    (unsigned int)__bfloat16_as_ushort(h00) |
                    ((unsigned int)__bfloat16_as_ushort(h01) << 16);
                *(unsigned int*)(dh + i1) =
                    (unsigned int)__bfloat16_as_ushort(h10) |
                    ((unsigned int)__bfloat16_as_ushort(h11) << 16);
                *(unsigned int*)(dl + i0) =
                    bfpack(x0 - __bfloat162float(h00), y0 - __bfloat162float(h01));
                *(unsigned int*)(dl + i1) =
                    bfpack(x1 - __bfloat162float(h10), y1 - __bfloat162float(h11));
            }
    } else {
        float* SV = (float*)smem;       // 128 cols x 132 rows
        __syncthreads();
        #pragma unroll
        for (int mf = 0; mf < 2; mf++)
            #pragma unroll
            for (int nf = 0; nf < 8; nf++) {
                int cl = warp_n * 64 + nf * 8 + (lane & 3) * 2;
                int rl = warp_m * 32 + mf * 16 + (lane >> 2);
                float b0 = bias[cBase + cl], b1 = bias[cBase + cl + 1];
                SV[cl * 132 + rl]       = acc[mf][nf][0] + b0;
                SV[(cl+1) * 132 + rl]   = acc[mf][nf][1] + b1;
                SV[cl * 132 + rl + 8]   = acc[mf][nf][2] + b0;
                SV[(cl+1) * 132 + rl+8] = acc[mf][nf][3] + b1;
            }
        __syncthreads();
        int ldf = tid >> 1;
        int s0  = (tid & 1) * 64;
        int gcol = cBase + ldf;
        int h = gcol >> 6, df = gcol & 63;
        int b_ = rBase >> 9, sBase = rBase & (SS - 1);
        size_t base = (((size_t)(b_ * HH + h) * DFF + df) * SS) + sBase + s0;
        #pragma unroll
        for (int u = 0; u < 64; u += 8) {
            float4 x = *(float4*)&SV[ldf * 132 + s0 + u];
            float4 y = *(float4*)&SV[ldf * 132 + s0 + u + 4];
            float vv[8] = {x.x, x.y, x.z, x.w, y.x, y.y, y.z, y.w};
            unsigned int hw[4], lw[4];
            #pragma unroll
            for (int i = 0; i < 4; i++) {
                __nv_bfloat16 p0 = __float2bfloat16(vv[2*i]);
                __nv_bfloat16 p1 = __float2bfloat16(vv[2*i+1]);
                hw[i] = (unsigned int)__bfloat16_as_ushort(p0) |
                        ((unsigned int)__bfloat16_as_ushort(p1) << 16);
                lw[i] = bfpack(vv[2*i] - __bfloat162float(p0),
                               vv[2*i+1] - __bfloat162float(p1));
            }
            *(uint4*)(g_Vh + base + u) = make_uint4(hw[0], hw[1], hw[2], hw[3]);
            *(uint4*)(g_Vl + base + u) = make_uint4(lw[0], lw[1], lw[2], lw[3]);
        }
    }
}

// ===========================================================================
// Attention: 64 q-rows per CTA, 512 threads (16 warps, 4m x 4n).
// 128-wide K/V j-tiles, DOUBLE-BUFFERED (load jt+1 overlaps compute jt).
// Output written bf16-split to g_Ah[0]/g_Al[0].
// ===========================================================================
#define AQ_H 0
#define AQ_L 8192
#define ASC  16384
#define SCR  2176              // row stride bytes (17*128)
#define AOP  155648            // two 32KB operand buffers (hi at +0, lo at +16384)
#define OPBUF(i) (AOP + (unsigned int)(i) * 32768u)
#define OPLO 16384
#define ATTN_SMEM_TOT 221184

__global__ __launch_bounds__(512)
void akt_attn_kernel(const float* __restrict__ gammas,
                     const int* __restrict__ zero_pad)
{
    extern __shared__ char smem[];
    const unsigned int sb = smem_to_u32(smem);
    const int tid = threadIdx.x, lane = tid & 31, wid = tid >> 5;
    const int bh = blockIdx.y, b = bh >> 3, h = bh & 7;
    const int q0 = blockIdx.x << 6, qmax = q0 + 63;
    const int njt = (qmax >> 7) + 1;              // 128-wide j-tiles
    const int ksmax16 = ((qmax >> 4) + 1) << 4;   // live k bound (16-aligned)
    const int wm = wid & 3, wn = wid >> 2;        // 4m x 4n

    const __nv_bfloat16* Qh = g_Qh + ((size_t)bh * SS + q0) * DFF;
    const __nv_bfloat16* Ql = g_Ql + ((size_t)bh * SS + q0) * DFF;
    const __nv_bfloat16* Kh = g_Kh + (size_t)bh * SS * DFF;
    const __nv_bfloat16* Kl = g_Kl + (size_t)bh * SS * DFF;
    const __nv_bfloat16* Vh = g_Vh + (size_t)bh * DFF * SS;
    const __nv_bfloat16* Vl = g_Vl + (size_t)bh * DFF * SS;

    // ---- group 0: Q (64x128B hi/lo) + K tile 0 ----
    {
        int row = tid >> 3, kc = tid & 7;
        unsigned int dsw = (unsigned int)(row * 128) +
                           (unsigned int)((kc ^ (row & 7)) << 4);
        cp_async16(sb + AQ_H + dsw, Qh + row * DFF + kc * 8);
        cp_async16(sb + AQ_L + dsw, Ql + row * DFF + kc * 8);
    }
    #pragma unroll
    for (int u = 0; u < 2; u++) {
        int c = u * 512 + tid;
        int row = c >> 3, kc = c & 7;   // row 0..127
        if (row <= qmax) {
            unsigned int dsw = (unsigned int)(row * 128) +
                               (unsigned int)((kc ^ (row & 7)) << 4);
            cp_async16(sb + OPBUF(0) + dsw, Kh + row * DFF + kc * 8);
            cp_async16(sb + OPBUF(0) + OPLO + dsw, Kl + row * DFF + kc * 8);
        }
    }
    CP_COMMIT();

    // Q fragments (hoisted; loaded after first wait)
    unsigned int qfh[4][4], qfl[4][4];

    // ---- Phase 1: scores via mma, double-buffered K tiles ----
    for (int jt = 0; jt < njt; jt++) {
        __syncthreads();     // prior compute finished (safe to overwrite buffer)
        if (jt + 1 < njt) {
            #pragma unroll
            for (int u = 0; u < 2; u++) {
                int c = u * 512 + tid;
                int row = c >> 3, kc = c & 7;
                int grow = (jt + 1) * 128 + row;
                if (grow <= qmax) {
                    unsigned int dsw = (unsigned int)(row * 128) +
                                       (unsigned int)((kc ^ (row & 7)) << 4);
                    cp_async16(sb + OPBUF((jt+1)&1) + dsw, Kh + grow * DFF + kc * 8);
                    cp_async16(sb + OPBUF((jt+1)&1) + OPLO + dsw, Kl + grow * DFF + kc * 8);
                }
            }
            CP_COMMIT();
            CP_WAIT1();
        } else {
            CP_WAIT0();
        }
        __syncthreads();     // tile jt visible

        if (jt == 0) {       // hoist Q fragments once
            #pragma unroll
            for (int ks = 0; ks < 4; ks++) {
                int row = wm * 16 + (lane & 15);
                int kc = ks * 2 + (lane >> 4);
                unsigned int ad = sb + (unsigned int)(row * 128) +
                                  (unsigned int)((kc ^ (row & 7)) << 4);
                ldmatrix_x4(qfh[ks], ad + AQ_H);
                ldmatrix_x4(qfl[ks], ad + AQ_L);
            }
        }

        if (jt * 128 + wn * 32 <= qmax) {   // warp-uniform liveness (32-col)
            const unsigned int kb = sb + OPBUF(jt & 1);
            float acc[4][4];
            #pragma unroll
            for (int nf = 0; nf < 4; nf++)
                #pragma unroll
                for (int i = 0; i < 4; i++) acc[nf][i] = 0.f;

            #pragma unroll
            for (int ks = 0; ks < 4; ks++) {
                unsigned int bhf[2][4], blf[2][4];
                #pragma unroll
                for (int p = 0; p < 2; p++) {
                    int row = wn * 32 + p * 16 + (lane & 7) + ((lane & 16) >> 1);
                    int kc = ks * 2 + ((lane >> 3) & 1);
                    unsigned int bd = kb + (unsigned int)(row * 128) +
                                      (unsigned int)((kc ^ (row & 7)) << 4);
                    ldmatrix_x4(bhf[p], bd);
                    ldmatrix_x4(blf[p], bd + OPLO);
                }
                #pragma unroll
                for (int nf = 0; nf < 4; nf++) {
                    int p = nf >> 1, hh = (nf & 1) * 2;
                    mma_bf16(acc[nf], qfh[ks], bhf[p][hh], bhf[p][hh+1]);
                    mma_bf16(acc[nf], qfh[ks], blf[p][hh], blf[p][hh+1]);
                    mma_bf16(acc[nf], qfl[ks], bhf[p][hh], bhf[p][hh+1]);
                }
            }
            int r0 = wm * 16 + (lane >> 2);
            #pragma unroll
            for (int nf = 0; nf < 4; nf++) {
                int col = jt * 128 + wn * 32 + nf * 8 + (lane & 3) * 2;
                unsigned int o0 = (unsigned int)(r0 * SCR) +
                    (unsigned int)((((col >> 2) ^ (r0 & 7)) << 4) + (col & 3) * 4);
                unsigned int o1 = o0 + 8 * SCR;
                *(float2*)(smem + ASC + o0) = make_float2(acc[nf][0], acc[nf][1]);
                *(float2*)(smem + ASC + o1) = make_float2(acc[nf][2], acc[nf][3]);
            }
        }
    }
    __syncthreads();

    // ---- kick V tile 0 load (overlaps phase 2) ----
    #pragma unroll
    for (int u = 0; u < 2; u++) {
        int c = u * 512 + tid;
        int row = c >> 4, kc = c & 15;     // row 0..63 (df), kc 0..15
        if (kc * 8 < ksmax16) {
            unsigned int dsw = (unsigned int)(row * 256) +
                               (unsigned int)((kc ^ (row & 7)) << 4);
            cp_async16(sb + OPBUF(0) + dsw, Vh + row * SS + kc * 8);
            cp_async16(sb + OPBUF(0) + OPLO + dsw, Vl + row * SS + kc * 8);
        }
    }
    CP_COMMIT();

    // ---- Phase 2 ----
    const float gamma = -log1pf(__expf(gammas[h]));
    const int zp = *zero_pad;
    const int nch3 = (ksmax16 + 31) >> 5;

    for (int pass = 0; pass < 4; pass++) {
        const int qr = (pass << 4) + wid;
        const int qg = q0 + qr;
        const int qtop = qg >> 5;
        const unsigned int rbase = (unsigned int)(qr * SCR);
        float sv[16], pv[16], tot[16];

        #pragma unroll
        for (int i = 0; i < 16; i++) {
            if (i <= qtop) {
                int j = (i << 5) + lane;
                unsigned int off = ((((j >> 2) ^ (qr & 7)) << 4) + (j & 3) * 4);
                sv[i] = *(float*)(smem + ASC + rbase + off);
            }
        }

        float m = -3.0e38f;
        #pragma unroll
        for (int i = 0; i < 16; i++) {
            if (i <= qtop) {
                int j = (i << 5) + lane;
                if (j <= qg) m = fmaxf(m, sv[i]);
            }
        }
        #pragma unroll
        for (int off = 16; off > 0; off >>= 1)
            m = fmaxf(m, __shfl_xor_sync(0xffffffffu, m, off));
        float ssum = 0.f;
        #pragma unroll
        for (int i = 0; i < 16; i++) {
            if (i <= qtop) {
                int j = (i << 5) + lane;
                pv[i] = (j <= qg) ? __expf(sv[i] - m) : 0.f;
                ssum += pv[i];
            }
        }
        #pragma unroll
        for (int off = 16; off > 0; off >>= 1)
            ssum += __shfl_xor_sync(0xffffffffu, ssum, off);
        const float inv1 = 1.f / ssum;

        #pragma unroll
        for (int i = 0; i < 16; i++) {
            if (i <= qtop) {
                float s = pv[i] * inv1;
                #pragma unroll
                for (int off = 1; off < 32; off <<= 1) {
                    float t = __shfl_up_sync(0xffffffffu, s, off);
                    if (lane >= off) s += t;
                }
                pv[i] = s;
                tot[i] = __shfl_sync(0xffffffffu, s, 31);
            }
        }
        const float* dfrow = g_DF + ((size_t)b * SS + qg) * SS;
        float pre = 0.f;
        #pragma unroll
        for (int i = 0; i < 16; i++) {
            if (i <= qtop) {
                int j = (i << 5) + lane;
                float c = pre + pv[i];
                pre += tot[i];
                float rem = fmaxf(1.f - c, 0.f);
                float dsc = (j <= qg) ? sqrtf(rem * (float)(qg - j)) : 0.f;
                float te = __expf(dsc * gamma * dfrow[j]);
                te = fminf(fmaxf(te, 1e-5f), 1e5f);
                pv[i] = (j <= qg) ? sv[i] * te : -3.0e38f;
            }
        }

        float m2 = -3.0e38f;
        #pragma unroll
        for (int i = 0; i < 16; i++)
            if (i <= qtop) m2 = fmaxf(m2, pv[i]);
        #pragma unroll
        for (int off = 16; off > 0; off >>= 1)
            m2 = fmaxf(m2, __shfl_xor_sync(0xffffffffu, m2, off));
        float sum2 = 0.f;
        #pragma unroll
        for (int i = 0; i < 16; i++) {
            if (i <= qtop) {
                int j = (i << 5) + lane;
                float e = (j <= qg) ? __expf(pv[i] - m2) : 0.f;
                sv[i] = e;
                sum2 += e;
            }
        }
        #pragma unroll
        for (int off = 16; off > 0; off >>= 1)
            sum2 += __shfl_xor_sync(0xffffffffu, sum2, off);
        const float inv2 = 1.f / sum2;
        const bool zrow = (zp != 0) && (qg == 0);

        // write P (bf16 hi/lo) aliased onto this row's SC bytes
        #pragma unroll
        for (int i = 0; i < 16; i++) {
            if (i < nch3) {
                int j = (i << 5) + lane;
                float pr = (i <= qtop && !zrow) ? sv[i] * inv2 : 0.f;
                __nv_bfloat16 ph = __float2bfloat16(pr);
                __nv_bfloat16 pl = __float2bfloat16(pr - __bfloat162float(ph));
                unsigned int off2 = (unsigned int)((((j >> 3) ^ (qr & 7)) << 4) +
                                                   ((j & 7) << 1));
                *(__nv_bfloat16*)(smem + ASC + rbase + off2) = ph;
                *(__nv_bfloat16*)(smem + ASC + rbase + 1024 + off2) = pl;
            }
        }
    }

    // ---- Phase 3: out = P @ V via mma, double-buffered V tiles ----
    float oacc[2][4];
    #pragma unroll
    for (int nf = 0; nf < 2; nf++)
        #pragma unroll
        for (int i = 0; i < 4; i++) oacc[nf][i] = 0.f;

    for (int jt = 0; jt < njt; jt++) {
        __syncthreads();     // prior compute / phase-2 P writes done
        if (jt + 1 < njt) {
            #pragma unroll
            for (int u = 0; u < 2; u++) {
                int c = u * 512 + tid;
                int row = c >> 4, kc = c & 15;
                if ((jt + 1) * 128 + kc * 8 < ksmax16) {
                    unsigned int dsw = (unsigned int)(row * 256) +
                                       (unsigned int)((kc ^ (row & 7)) << 4);
                    cp_async16(sb + OPBUF((jt+1)&1) + dsw,
                               Vh + row * SS + (jt+1)*128 + kc * 8);
                    cp_async16(sb + OPBUF((jt+1)&1) + OPLO + dsw,
                               Vl + row * SS + (jt+1)*128 + kc * 8);
                }
            }
            CP_COMMIT();
            CP_WAIT1();
        } else {
            CP_WAIT0();
        }
        __syncthreads();     // V tile jt visible

        const unsigned int vb = sb + OPBUF(jt & 1);
        const int kslim = min(8, (ksmax16 >> 4) - jt * 8);
        for (int ks = 0; ks < kslim; ks++) {
            unsigned int ph[4], pl[4], vh[4], vl[4];
            {
                int row = wm * 16 + (lane & 15);
                int kc = jt * 16 + ks * 2 + (lane >> 4);
                unsigned int ad = sb + ASC + (unsigned int)(row * SCR) +
                                  (unsigned int)((kc ^ (row & 7)) << 4);
                ldmatrix_x4(ph, ad);
                ldmatrix_x4(pl, ad + 1024);
            }
            {
                int row = wn * 16 + (lane & 7) + ((lane & 16) >> 1);
                int kc = ks * 2 + ((lane >> 3) & 1);
                unsigned int bd = vb + (unsigned int)(row * 256) +
                                  (unsigned int)((kc ^ (row & 7)) << 4);
                ldmatrix_x4(vh, bd);
                ldmatrix_x4(vl, bd + OPLO);
            }
            #pragma unroll
            for (int nf = 0; nf < 2; nf++) {
                int hh = nf * 2;
                mma_bf16(oacc[nf], ph, vh[hh], vh[hh+1]);
                mma_bf16(oacc[nf], pl, vh[hh], vh[hh+1]);
                mma_bf16(oacc[nf], ph, vl[hh], vl[hh+1]);
            }
        }
    }

    // epilogue: bf16 hi/lo split straight into g_Ah[0]/g_Al[0]  [B,S,D]
    {
        int row = q0 + wm * 16 + (lane >> 2);
        #pragma unroll
        for (int nf = 0; nf < 2; nf++) {
            int col = h * 64 + wn * 16 + nf * 8 + (lane & 3) * 2;
            size_t i0 = ((size_t)(b * SS + row)     * DD) + col;
            size_t i1 = ((size_t)(b * SS + row + 8) * DD) + col;
            float x0 = oacc[nf][0], y0 = oacc[nf][1];
            float x1 = oacc[nf][2], y1 = oacc[nf][3];
            __nv_bfloat16 h00 = __float2bfloat16(x0), h01 = __float2bfloat16(y0);
            __nv_bfloat16 h10 = __float2bfloat16(x1), h11 = __float2bfloat16(y1);
            *(unsigned int*)(g_Ah[0] + i0) =
                (unsigned int)__bfloat16_as_ushort(h00) |
                ((unsigned int)__bfloat16_as_ushort(h01) << 16);
            *(unsigned int*)(g_Ah[0] + i1) =
                (unsigned int)__bfloat16_as_ushort(h10) |
                ((unsigned int)__bfloat16_as_ushort(h11) << 16);
            *(unsigned int*)(g_Al[0] + i0) =
                bfpack(x0 - __bfloat162float(h00), y0 - __bfloat162float(h01));
            *(unsigned int*)(g_Al[0] + i1) =
                bfpack(x1 - __bfloat162float(h10), y1 - __bfloat162float(h11));
        }
    }
}

// ---------------------------------------------------------------------------
extern "C" void kernel_launch(void* const* d_in, const int* in_sizes, int n_in,
                              void* d_out, int out_size)
{
    const float* q      = (const float*)d_in[0];
    const float* k      = (const float*)d_in[1];
    const float* v      = (const float*)d_in[2];
    const int*   zero_pad = (const int*)d_in[4];
    const float* qd     = (const float*)d_in[5];
    const float* Wk     = (const float*)d_in[6];
    const float* bk     = (const float*)d_in[7];
    const float* Wv     = (const float*)d_in[8];
    const float* bv     = (const float*)d_in[9];
    const float* Wo     = (const float*)d_in[10];
    const float* bo     = (const float*)d_in[11];
    const float* gammas = (const float*)d_in[12];
    float* out = (float*)d_out;

    const int GEMM_SMEM = 3 * STG_STRIDE;    // 98304 B
    cudaFuncSetAttribute(gemm_mma_kernel<1>,
                         cudaFuncAttributeMaxDynamicSharedMemorySize, GEMM_SMEM);
    cudaFuncSetAttribute(gemm_mma_kernel<0>,
                         cudaFuncAttributeMaxDynamicSharedMemorySize, GEMM_SMEM);
    cudaFuncSetAttribute(akt_attn_kernel,
                         cudaFuncAttributeMaxDynamicSharedMemorySize, ATTN_SMEM_TOT);

    const int N_IN = BB * SS * DD;
    const int N_QD = BB * SS * SS;
    const int N_W  = DD * DD;

    convert_split<<<N_IN / 2048, 256>>>(q,  0, N_IN);
    convert_split<<<N_IN / 2048, 256>>>(k,  1, N_IN);
    convert_split<<<N_IN / 2048, 256>>>(v,  2, N_IN);
    convert_split<<<N_W  / 2048, 256>>>(Wk, 3, N_W);
    convert_split<<<N_W  / 2048, 256>>>(Wv, 4, N_W);
    convert_split<<<N_W  / 2048, 256>>>(Wo, 5, N_W);
    diff_kernel<<<N_QD / 1024, 256>>>(qd);

    gemm_mma_kernel<1><<<dim3(128, 4, 3), 256, GEMM_SMEM>>>(bk, bv, nullptr);

    akt_attn_kernel<<<dim3(8, 256), 512, ATTN_SMEM_TOT>>>(gammas, zero_pad);

    gemm_mma_kernel<0><<<dim3(128, 4, 1), 256, GEMM_SMEM>>>(bo, nullptr, out);
}